// round 2
// baseline (speedup 1.0000x reference)
#include <cuda_runtime.h>
#include <cuda_bf16.h>
#include <cstddef>

// Problem constants
#define BATCH 8
#define SLEN 1024
#define DMODEL 1024
#define NHEADS 16
#define DK 64
#define MROWS (BATCH * SLEN)   // 8192

// ---------------- scratch (device globals; no allocation allowed) ------------
__device__ float g_Q[MROWS * DMODEL];
__device__ float g_K[MROWS * DMODEL];
__device__ float g_V[MROWS * DMODEL];
__device__ float g_X[MROWS * DMODEL];

// ---------------- generic fp32 NT GEMM:  C[M,N] = A[M,K] @ W[N,K]^T + bias ---
#define BM 128
#define BN 128
#define BK 16
#define SSTR (BM + 4)   // 132: 4-way max bank conflict on transpose stores

__global__ __launch_bounds__(256) void gemm_nt_kernel(
    const float* __restrict__ A, const float* __restrict__ W,
    const float* __restrict__ bias, float* __restrict__ C,
    int M, int N, int K)
{
    __shared__ float As[BK][SSTR];
    __shared__ float Ws[BK][SSTR];

    const int bm = blockIdx.y * BM;
    const int bn = blockIdx.x * BN;
    const int tid = threadIdx.x;
    const int tx = tid & 15;
    const int ty = tid >> 4;
    const int m0 = ty * 8;
    const int n0 = tx * 8;

    float acc[8][8];
#pragma unroll
    for (int i = 0; i < 8; i++)
#pragma unroll
        for (int j = 0; j < 8; j++) acc[i][j] = 0.f;

    for (int k0 = 0; k0 < K; k0 += BK) {
        // load 128x16 A-tile and W-tile, transposed into smem
#pragma unroll
        for (int v = 0; v < 2; v++) {
            int vid = tid * 2 + v;       // 0..511
            int row = vid >> 2;          // 0..127
            int kc  = (vid & 3) * 4;     // 0,4,8,12
            float4 a4 = *(const float4*)&A[(size_t)(bm + row) * K + k0 + kc];
            As[kc + 0][row] = a4.x; As[kc + 1][row] = a4.y;
            As[kc + 2][row] = a4.z; As[kc + 3][row] = a4.w;
            float4 w4 = *(const float4*)&W[(size_t)(bn + row) * K + k0 + kc];
            Ws[kc + 0][row] = w4.x; Ws[kc + 1][row] = w4.y;
            Ws[kc + 2][row] = w4.z; Ws[kc + 3][row] = w4.w;
        }
        __syncthreads();

#pragma unroll
        for (int k = 0; k < BK; k++) {
            float a[8], b[8];
            *(float4*)&a[0] = *(float4*)&As[k][m0];
            *(float4*)&a[4] = *(float4*)&As[k][m0 + 4];
            *(float4*)&b[0] = *(float4*)&Ws[k][n0];
            *(float4*)&b[4] = *(float4*)&Ws[k][n0 + 4];
#pragma unroll
            for (int i = 0; i < 8; i++)
#pragma unroll
                for (int j = 0; j < 8; j++)
                    acc[i][j] += a[i] * b[j];
        }
        __syncthreads();
    }

    // epilogue: add bias, store
#pragma unroll
    for (int i = 0; i < 8; i++) {
        size_t rbase = (size_t)(bm + m0 + i) * N + bn + n0;
#pragma unroll
        for (int j = 0; j < 8; j += 4) {
            float4 o;
            o.x = acc[i][j + 0] + bias[bn + n0 + j + 0];
            o.y = acc[i][j + 1] + bias[bn + n0 + j + 1];
            o.z = acc[i][j + 2] + bias[bn + n0 + j + 2];
            o.w = acc[i][j + 3] + bias[bn + n0 + j + 3];
            *(float4*)&C[rbase + j] = o;
        }
    }
}

// ---------------- attention kernel ------------------------------------------
// Per block: (b, h, 64-row q tile). Computes
//   x = (exp(QK^T/8)*pol @ V + (EPS/S)*colsum(V)) / (rowsum(exp*pol) + EPS)
#define QT 64
#define KT 64
#define ASTR 68   // smem row stride (floats)

__global__ __launch_bounds__(256) void attn_kernel(
    const float* __restrict__ Q, const float* __restrict__ K,
    const float* __restrict__ V, const float* __restrict__ pol,
    float* __restrict__ X)
{
    extern __shared__ float sm[];
    float* Qs = sm;                    // [d][q] 64x68
    float* Ks = Qs + 64 * ASTR;        // [d][k]
    float* Ss = Ks + 64 * ASTR;        // [q][k]
    float* Vs = Ss + 64 * ASTR;        // [k][d]
    float* pols = Vs + 64 * ASTR;      // [64]

    const int qt = blockIdx.x;
    const int h  = blockIdx.y;
    const int b  = blockIdx.z;
    const int tid = threadIdx.x;
    const int tx = tid & 15;
    const int ty = tid >> 4;
    const int q0 = ty * 4;
    const int c0 = tx * 4;  // k-col in phase1, d-col in phase2

    const float* Qbase = Q + ((size_t)b * SLEN + qt * QT) * DMODEL + h * DK;
    const float* Kbase = K + (size_t)b * SLEN * DMODEL + h * DK;
    const float* Vbase = V + (size_t)b * SLEN * DMODEL + h * DK;
    const float* polb  = pol + (size_t)b * SLEN;

    // load Q tile transposed [d][q]
    for (int i = tid; i < QT * DK; i += 256) {
        int r = i >> 6, d = i & 63;
        Qs[d * ASTR + r] = Qbase[(size_t)r * DMODEL + d];
    }

    float acc[4][4];
    float rsum[4] = {0.f, 0.f, 0.f, 0.f};
    float vsum[4] = {0.f, 0.f, 0.f, 0.f};
#pragma unroll
    for (int i = 0; i < 4; i++)
#pragma unroll
        for (int j = 0; j < 4; j++) acc[i][j] = 0.f;

    __syncthreads();

    for (int kt = 0; kt < SLEN / KT; kt++) {
        const float* Kb = Kbase + (size_t)kt * KT * DMODEL;
        const float* Vb = Vbase + (size_t)kt * KT * DMODEL;
        for (int i = tid; i < KT * DK; i += 256) {
            int r = i >> 6, d = i & 63;
            float kv = Kb[(size_t)r * DMODEL + d];
            float vv = Vb[(size_t)r * DMODEL + d];
            Ks[d * ASTR + r] = kv;
            Vs[r * ASTR + d] = vv;
        }
        if (tid < KT) pols[tid] = polb[kt * KT + tid];
        __syncthreads();

        // phase 1: S = Q @ K^T  (64x64 over d=64)
        float s[4][4];
#pragma unroll
        for (int i = 0; i < 4; i++)
#pragma unroll
            for (int j = 0; j < 4; j++) s[i][j] = 0.f;

#pragma unroll 8
        for (int d = 0; d < DK; d++) {
            float4 a4 = *(float4*)&Qs[d * ASTR + q0];
            float4 b4 = *(float4*)&Ks[d * ASTR + c0];
            float a[4] = {a4.x, a4.y, a4.z, a4.w};
            float bb[4] = {b4.x, b4.y, b4.z, b4.w};
#pragma unroll
            for (int i = 0; i < 4; i++)
#pragma unroll
                for (int j = 0; j < 4; j++)
                    s[i][j] += a[i] * bb[j];
        }

        // exp * policy, stage into Ss
#pragma unroll
        for (int i = 0; i < 4; i++) {
            float4 e;
            e.x = __expf(s[i][0] * 0.125f) * pols[c0 + 0];
            e.y = __expf(s[i][1] * 0.125f) * pols[c0 + 1];
            e.z = __expf(s[i][2] * 0.125f) * pols[c0 + 2];
            e.w = __expf(s[i][3] * 0.125f) * pols[c0 + 3];
            *(float4*)&Ss[(q0 + i) * ASTR + c0] = e;
        }
        __syncthreads();

        // phase 2: acc += Ss @ Vs ; rowsum(Ss) ; colsum(Vs)
#pragma unroll 8
        for (int kk = 0; kk < KT; kk++) {
            float4 v4 = *(float4*)&Vs[kk * ASTR + c0];
            float vv[4] = {v4.x, v4.y, v4.z, v4.w};
            float sv[4];
#pragma unroll
            for (int i = 0; i < 4; i++) sv[i] = Ss[(q0 + i) * ASTR + kk];
#pragma unroll
            for (int i = 0; i < 4; i++) {
#pragma unroll
                for (int j = 0; j < 4; j++)
                    acc[i][j] += sv[i] * vv[j];
                rsum[i] += sv[i];
            }
#pragma unroll
            for (int j = 0; j < 4; j++) vsum[j] += vv[j];
        }
        __syncthreads();
    }

    // epilogue
    const float ceps = 1e-6f / (float)SLEN;
    float* Xb = X + ((size_t)b * SLEN + qt * QT) * DMODEL + h * DK;
#pragma unroll
    for (int i = 0; i < 4; i++) {
        float inv = 1.f / (rsum[i] + 1e-6f);
        float4 o;
        o.x = (acc[i][0] + ceps * vsum[0]) * inv;
        o.y = (acc[i][1] + ceps * vsum[1]) * inv;
        o.z = (acc[i][2] + ceps * vsum[2]) * inv;
        o.w = (acc[i][3] + ceps * vsum[3]) * inv;
        *(float4*)&Xb[(size_t)(q0 + i) * DMODEL + c0] = o;
    }
}

// ---------------- launch ------------------------------------------------------
extern "C" void kernel_launch(void* const* d_in, const int* in_sizes, int n_in,
                              void* d_out, int out_size)
{
    const float* query   = (const float*)d_in[0];
    const float* key     = (const float*)d_in[1];
    const float* value   = (const float*)d_in[2];
    const float* policy  = (const float*)d_in[3];
    const float* wq_w    = (const float*)d_in[4];
    const float* wq_b    = (const float*)d_in[5];
    const float* wk_w    = (const float*)d_in[6];
    const float* wk_b    = (const float*)d_in[7];
    const float* wv_w    = (const float*)d_in[8];
    const float* wv_b    = (const float*)d_in[9];
    const float* dense_w = (const float*)d_in[10];
    const float* dense_b = (const float*)d_in[11];
    float* out = (float*)d_out;

    float *Qp, *Kp, *Vp, *Xp;
    cudaGetSymbolAddress((void**)&Qp, g_Q);
    cudaGetSymbolAddress((void**)&Kp, g_K);
    cudaGetSymbolAddress((void**)&Vp, g_V);
    cudaGetSymbolAddress((void**)&Xp, g_X);

    dim3 gblk(DMODEL / BN, MROWS / BM);  // (8, 64)
    gemm_nt_kernel<<<gblk, 256>>>(query, wq_w, wq_b, Qp, MROWS, DMODEL, DMODEL);
    gemm_nt_kernel<<<gblk, 256>>>(key,   wk_w, wk_b, Kp, MROWS, DMODEL, DMODEL);
    gemm_nt_kernel<<<gblk, 256>>>(value, wv_w, wv_b, Vp, MROWS, DMODEL, DMODEL);

    int smem = (4 * 64 * ASTR + 64) * (int)sizeof(float);  // ~70 KB
    cudaFuncSetAttribute(attn_kernel, cudaFuncAttributeMaxDynamicSharedMemorySize, smem);
    dim3 gattn(SLEN / QT, NHEADS, BATCH);  // (16, 16, 8)
    attn_kernel<<<gattn, 256, smem>>>(Qp, Kp, Vp, policy, Xp);

    gemm_nt_kernel<<<gblk, 256>>>(Xp, dense_w, dense_b, out, MROWS, DMODEL, DMODEL);
}

// round 4
// speedup vs baseline: 1.7093x; 1.7093x over previous
#include <cuda_runtime.h>
#include <cuda_bf16.h>
#include <cstdint>
#include <cstddef>

// Problem constants
#define BATCH 8
#define SLEN 1024
#define DMODEL 1024
#define NHEADS 16
#define DK 64
#define MROWS (BATCH * SLEN)   // 8192

// ---------------- scratch (device globals; no allocation allowed) ------------
__device__ float g_Q[MROWS * DMODEL];
__device__ float g_K[MROWS * DMODEL];
__device__ float g_V[MROWS * DMODEL];
__device__ float g_X[MROWS * DMODEL];

// =================== PTX helpers =============================================
static __device__ __forceinline__ uint32_t smem_u32(const void* p) {
    uint32_t a;
    asm("{ .reg .u64 t; cvta.to.shared.u64 t, %1; cvt.u32.u64 %0, t; }"
        : "=r"(a) : "l"(p));
    return a;
}

#define CP_ASYNC16(dst, src) \
    asm volatile("cp.async.cg.shared.global [%0], [%1], 16;" \
                 :: "r"(dst), "l"(src) : "memory")
#define CP_COMMIT() asm volatile("cp.async.commit_group;" ::: "memory")
#define CP_WAIT2()  asm volatile("cp.async.wait_group 2;" ::: "memory")

static __device__ __forceinline__ uint32_t f2tf32(float x) {
    uint32_t r;
    asm("cvt.rna.tf32.f32 %0, %1;" : "=r"(r) : "f"(x));
    return r;
}

#define LDSM_X4(r0, r1, r2, r3, addr) \
    asm volatile("ldmatrix.sync.aligned.m8n8.x4.shared.b16 {%0,%1,%2,%3}, [%4];" \
                 : "=r"(r0), "=r"(r1), "=r"(r2), "=r"(r3) : "r"(addr))

#define MMA_TF32(c, a, b) \
    asm volatile("mma.sync.aligned.m16n8k8.row.col.f32.tf32.tf32.f32 " \
                 "{%0,%1,%2,%3}, {%4,%5,%6,%7}, {%8,%9}, {%0,%1,%2,%3};" \
                 : "+f"((c)[0]), "+f"((c)[1]), "+f"((c)[2]), "+f"((c)[3]) \
                 : "r"((a)[0]), "r"((a)[1]), "r"((a)[2]), "r"((a)[3]), \
                   "r"((b)[0]), "r"((b)[1]))

// =================== tf32 mma.sync NT GEMM ===================================
// C[M,N] = A[M,K] @ W[N,K]^T + bias.  CTA 128x128, BK=32, 4-stage cp.async.
// 8 warps as 2(M) x 4(N); warp tile 64x32; mma m16n8k8 tf32.
#define GSTAGES 4
#define ASTRIDE 36                       // padded fp32 row stride (LDSM conflict-free)
#define ATILE_WORDS (128 * ASTRIDE)      // 4608 words = 18432 B
#define STAGE_BYTES (2 * ATILE_WORDS * 4) // A tile + B tile = 36864 B
#define GEMM_SMEM (GSTAGES * STAGE_BYTES) // 147456 B

__global__ __launch_bounds__(256) void gemm_mma(
    const float* __restrict__ A, const float* __restrict__ W,
    const float* __restrict__ bias, float* __restrict__ C,
    int M, int N, int K)
{
    extern __shared__ float dynf[];
    const uint32_t smbase = smem_u32(dynf);

    const int bm = blockIdx.y * 128;
    const int bn = blockIdx.x * 128;
    const int tid = threadIdx.x;
    const int wid = tid >> 5;
    const int lane = tid & 31;
    const int g = lane >> 2;       // group id 0..7
    const int t = lane & 3;        // thread-in-group
    const int warp_m = wid >> 2;   // 0..1
    const int warp_n = wid & 3;    // 0..3
    const int mbase = warp_m * 64;
    const int nbase = warp_n * 32;
    // ldmatrix per-thread source row/col within warp tile
    const int lrow = ((lane >> 3) & 1) * 8 + (lane & 7);
    const int lcolb = (lane >> 4) * 16;    // byte offset: 0 or 16 (4 fp32)

    const int nchunks = K / 32;    // 32

    const float* Abase = A + (size_t)bm * K;
    const float* Bbase = W + (size_t)bn * K;

    auto load_chunk = [&](int c, int s) {
        uint32_t sa = smbase + s * STAGE_BYTES;
        uint32_t sb = sa + ATILE_WORDS * 4;
        const float* Ap = Abase + c * 32;
        const float* Bp = Bbase + c * 32;
#pragma unroll
        for (int v = 0; v < 4; v++) {
            int idx = tid + 256 * v;       // 0..1023
            int row = idx >> 3;            // 0..127
            int seg = idx & 7;             // 16B segment in 128B row
            uint32_t off = (uint32_t)(row * ASTRIDE + seg * 4) * 4;
            CP_ASYNC16(sa + off, Ap + (size_t)row * K + seg * 4);
            CP_ASYNC16(sb + off, Bp + (size_t)row * K + seg * 4);
        }
    };

    float c[4][4][4];
#pragma unroll
    for (int mt = 0; mt < 4; mt++)
#pragma unroll
        for (int nt = 0; nt < 4; nt++)
#pragma unroll
            for (int r = 0; r < 4; r++) c[mt][nt][r] = 0.f;

    // prologue: stages 0..2
    for (int cc = 0; cc < GSTAGES - 1; cc++) {
        load_chunk(cc, cc);
        CP_COMMIT();
    }

    for (int i = 0; i < nchunks; i++) {
        const int s = i & (GSTAGES - 1);
        CP_WAIT2();
        __syncthreads();

        const int nxt = i + GSTAGES - 1;
        if (nxt < nchunks) load_chunk(nxt, nxt & (GSTAGES - 1));
        CP_COMMIT();

        // compute chunk i from stage s
        const uint32_t sa = smbase + s * STAGE_BYTES;
        const float* Bs = dynf + s * (STAGE_BYTES / 4) + ATILE_WORDS;

#pragma unroll
        for (int ks = 0; ks < 4; ks++) {
            uint32_t a[4][4];
#pragma unroll
            for (int mt = 0; mt < 4; mt++) {
                uint32_t addr = sa +
                    (uint32_t)((mbase + mt * 16 + lrow) * ASTRIDE + ks * 8) * 4 + lcolb;
                LDSM_X4(a[mt][0], a[mt][1], a[mt][2], a[mt][3], addr);
            }
            uint32_t b[4][2];
#pragma unroll
            for (int nt = 0; nt < 4; nt++) {
                const float* bp = Bs + (nbase + nt * 8 + g) * ASTRIDE + ks * 8 + t;
                b[nt][0] = f2tf32(bp[0]);
                b[nt][1] = f2tf32(bp[4]);
            }
#pragma unroll
            for (int mt = 0; mt < 4; mt++)
#pragma unroll
                for (int r = 0; r < 4; r++)
                    a[mt][r] = f2tf32(__uint_as_float(a[mt][r]));
#pragma unroll
            for (int mt = 0; mt < 4; mt++)
#pragma unroll
                for (int nt = 0; nt < 4; nt++)
                    MMA_TF32(c[mt][nt], a[mt], b[nt]);
        }
    }

    // epilogue: bias + store. c0/c1 at (row g, col 2t/2t+1), c2/c3 at row g+8.
#pragma unroll
    for (int mt = 0; mt < 4; mt++) {
        const int r0 = bm + mbase + mt * 16 + g;
#pragma unroll
        for (int nt = 0; nt < 4; nt++) {
            const int col = bn + nbase + nt * 8 + 2 * t;
            const float b0 = bias[col], b1 = bias[col + 1];
            float2 o0 = make_float2(c[mt][nt][0] + b0, c[mt][nt][1] + b1);
            float2 o1 = make_float2(c[mt][nt][2] + b0, c[mt][nt][3] + b1);
            *(float2*)&C[(size_t)r0 * N + col] = o0;
            *(float2*)&C[(size_t)(r0 + 8) * N + col] = o1;
        }
    }
}

// ---------------- attention kernel (unchanged, known-good) -------------------
#define QT 64
#define KT 64
#define ASTR 68

__global__ __launch_bounds__(256) void attn_kernel(
    const float* __restrict__ Q, const float* __restrict__ K,
    const float* __restrict__ V, const float* __restrict__ pol,
    float* __restrict__ X)
{
    extern __shared__ float sm[];
    float* Qs = sm;
    float* Ks = Qs + 64 * ASTR;
    float* Ss = Ks + 64 * ASTR;
    float* Vs = Ss + 64 * ASTR;
    float* pols = Vs + 64 * ASTR;

    const int qt = blockIdx.x;
    const int h  = blockIdx.y;
    const int b  = blockIdx.z;
    const int tid = threadIdx.x;
    const int tx = tid & 15;
    const int ty = tid >> 4;
    const int q0 = ty * 4;
    const int c0 = tx * 4;

    const float* Qbase = Q + ((size_t)b * SLEN + qt * QT) * DMODEL + h * DK;
    const float* Kbase = K + (size_t)b * SLEN * DMODEL + h * DK;
    const float* Vbase = V + (size_t)b * SLEN * DMODEL + h * DK;
    const float* polb  = pol + (size_t)b * SLEN;

    for (int i = tid; i < QT * DK; i += 256) {
        int r = i >> 6, d = i & 63;
        Qs[d * ASTR + r] = Qbase[(size_t)r * DMODEL + d];
    }

    float acc[4][4];
    float rsum[4] = {0.f, 0.f, 0.f, 0.f};
    float vsum[4] = {0.f, 0.f, 0.f, 0.f};
#pragma unroll
    for (int i = 0; i < 4; i++)
#pragma unroll
        for (int j = 0; j < 4; j++) acc[i][j] = 0.f;

    __syncthreads();

    for (int kt = 0; kt < SLEN / KT; kt++) {
        const float* Kb = Kbase + (size_t)kt * KT * DMODEL;
        const float* Vb = Vbase + (size_t)kt * KT * DMODEL;
        for (int i = tid; i < KT * DK; i += 256) {
            int r = i >> 6, d = i & 63;
            float kv = Kb[(size_t)r * DMODEL + d];
            float vv = Vb[(size_t)r * DMODEL + d];
            Ks[d * ASTR + r] = kv;
            Vs[r * ASTR + d] = vv;
        }
        if (tid < KT) pols[tid] = polb[kt * KT + tid];
        __syncthreads();

        float s[4][4];
#pragma unroll
        for (int i = 0; i < 4; i++)
#pragma unroll
            for (int j = 0; j < 4; j++) s[i][j] = 0.f;

#pragma unroll 8
        for (int d = 0; d < DK; d++) {
            float4 a4 = *(float4*)&Qs[d * ASTR + q0];
            float4 b4 = *(float4*)&Ks[d * ASTR + c0];
            float a[4] = {a4.x, a4.y, a4.z, a4.w};
            float bb[4] = {b4.x, b4.y, b4.z, b4.w};
#pragma unroll
            for (int i = 0; i < 4; i++)
#pragma unroll
                for (int j = 0; j < 4; j++)
                    s[i][j] += a[i] * bb[j];
        }

#pragma unroll
        for (int i = 0; i < 4; i++) {
            float4 e;
            e.x = __expf(s[i][0] * 0.125f) * pols[c0 + 0];
            e.y = __expf(s[i][1] * 0.125f) * pols[c0 + 1];
            e.z = __expf(s[i][2] * 0.125f) * pols[c0 + 2];
            e.w = __expf(s[i][3] * 0.125f) * pols[c0 + 3];
            *(float4*)&Ss[(q0 + i) * ASTR + c0] = e;
        }
        __syncthreads();

#pragma unroll 8
        for (int kk = 0; kk < KT; kk++) {
            float4 v4 = *(float4*)&Vs[kk * ASTR + c0];
            float vv[4] = {v4.x, v4.y, v4.z, v4.w};
            float sv[4];
#pragma unroll
            for (int i = 0; i < 4; i++) sv[i] = Ss[(q0 + i) * ASTR + kk];
#pragma unroll
            for (int i = 0; i < 4; i++) {
#pragma unroll
                for (int j = 0; j < 4; j++)
                    acc[i][j] += sv[i] * vv[j];
                rsum[i] += sv[i];
            }
#pragma unroll
            for (int j = 0; j < 4; j++) vsum[j] += vv[j];
        }
        __syncthreads();
    }

    const float ceps = 1e-6f / (float)SLEN;
    float* Xb = X + ((size_t)b * SLEN + qt * QT) * DMODEL + h * DK;
#pragma unroll
    for (int i = 0; i < 4; i++) {
        float inv = 1.f / (rsum[i] + 1e-6f);
        float4 o;
        o.x = (acc[i][0] + ceps * vsum[0]) * inv;
        o.y = (acc[i][1] + ceps * vsum[1]) * inv;
        o.z = (acc[i][2] + ceps * vsum[2]) * inv;
        o.w = (acc[i][3] + ceps * vsum[3]) * inv;
        *(float4*)&Xb[(size_t)(q0 + i) * DMODEL + c0] = o;
    }
}

// ---------------- launch ------------------------------------------------------
extern "C" void kernel_launch(void* const* d_in, const int* in_sizes, int n_in,
                              void* d_out, int out_size)
{
    const float* query   = (const float*)d_in[0];
    const float* key     = (const float*)d_in[1];
    const float* value   = (const float*)d_in[2];
    const float* policy  = (const float*)d_in[3];
    const float* wq_w    = (const float*)d_in[4];
    const float* wq_b    = (const float*)d_in[5];
    const float* wk_w    = (const float*)d_in[6];
    const float* wk_b    = (const float*)d_in[7];
    const float* wv_w    = (const float*)d_in[8];
    const float* wv_b    = (const float*)d_in[9];
    const float* dense_w = (const float*)d_in[10];
    const float* dense_b = (const float*)d_in[11];
    float* out = (float*)d_out;

    float *Qp, *Kp, *Vp, *Xp;
    cudaGetSymbolAddress((void**)&Qp, g_Q);
    cudaGetSymbolAddress((void**)&Kp, g_K);
    cudaGetSymbolAddress((void**)&Vp, g_V);
    cudaGetSymbolAddress((void**)&Xp, g_X);

    cudaFuncSetAttribute(gemm_mma, cudaFuncAttributeMaxDynamicSharedMemorySize, GEMM_SMEM);

    dim3 gblk(DMODEL / 128, MROWS / 128);  // (8, 64)
    gemm_mma<<<gblk, 256, GEMM_SMEM>>>(query, wq_w, wq_b, Qp, MROWS, DMODEL, DMODEL);
    gemm_mma<<<gblk, 256, GEMM_SMEM>>>(key,   wk_w, wk_b, Kp, MROWS, DMODEL, DMODEL);
    gemm_mma<<<gblk, 256, GEMM_SMEM>>>(value, wv_w, wv_b, Vp, MROWS, DMODEL, DMODEL);

    int smem = (4 * 64 * ASTR + 64) * (int)sizeof(float);
    cudaFuncSetAttribute(attn_kernel, cudaFuncAttributeMaxDynamicSharedMemorySize, smem);
    dim3 gattn(SLEN / QT, NHEADS, BATCH);  // (16, 16, 8)
    attn_kernel<<<gattn, 256, smem>>>(Qp, Kp, Vp, policy, Xp);

    gemm_mma<<<gblk, 256, GEMM_SMEM>>>(Xp, dense_w, dense_b, out, MROWS, DMODEL, DMODEL);
}

// round 5
// speedup vs baseline: 3.0753x; 1.7992x over previous
#include <cuda_runtime.h>
#include <cuda_bf16.h>
#include <cstdint>
#include <cstddef>

// Problem constants
#define BATCH 8
#define SLEN 1024
#define DMODEL 1024
#define NHEADS 16
#define DK 64
#define MROWS (BATCH * SLEN)   // 8192

// ---------------- scratch (device globals; no allocation allowed) ------------
__device__ float g_Q[MROWS * DMODEL];
__device__ float g_K[MROWS * DMODEL];
__device__ float g_V[MROWS * DMODEL];
__device__ float g_X[MROWS * DMODEL];

// =================== PTX helpers =============================================
static __device__ __forceinline__ uint32_t smem_u32(const void* p) {
    uint32_t a;
    asm("{ .reg .u64 t; cvta.to.shared.u64 t, %1; cvt.u32.u64 %0, t; }"
        : "=r"(a) : "l"(p));
    return a;
}

#define CP_ASYNC16(dst, src) \
    asm volatile("cp.async.cg.shared.global [%0], [%1], 16;" \
                 :: "r"(dst), "l"(src) : "memory")
#define CP_COMMIT() asm volatile("cp.async.commit_group;" ::: "memory")
#define CP_WAIT2()  asm volatile("cp.async.wait_group 2;" ::: "memory")
#define CP_WAIT1()  asm volatile("cp.async.wait_group 1;" ::: "memory")

static __device__ __forceinline__ uint32_t f2tf32(float x) {
    uint32_t r;
    asm("cvt.rna.tf32.f32 %0, %1;" : "=r"(r) : "f"(x));
    return r;
}

#define LDSM_X4(r0, r1, r2, r3, addr) \
    asm volatile("ldmatrix.sync.aligned.m8n8.x4.shared.b16 {%0,%1,%2,%3}, [%4];" \
                 : "=r"(r0), "=r"(r1), "=r"(r2), "=r"(r3) : "r"(addr))

#define MMA_TF32(c, a, b) \
    asm volatile("mma.sync.aligned.m16n8k8.row.col.f32.tf32.tf32.f32 " \
                 "{%0,%1,%2,%3}, {%4,%5,%6,%7}, {%8,%9}, {%0,%1,%2,%3};" \
                 : "+f"((c)[0]), "+f"((c)[1]), "+f"((c)[2]), "+f"((c)[3]) \
                 : "r"((a)[0]), "r"((a)[1]), "r"((a)[2]), "r"((a)[3]), \
                   "r"((b)[0]), "r"((b)[1]))

#define MMA_TF32_4(c, a0, a1, a2, a3, b0, b1) \
    asm volatile("mma.sync.aligned.m16n8k8.row.col.f32.tf32.tf32.f32 " \
                 "{%0,%1,%2,%3}, {%4,%5,%6,%7}, {%8,%9}, {%0,%1,%2,%3};" \
                 : "+f"((c)[0]), "+f"((c)[1]), "+f"((c)[2]), "+f"((c)[3]) \
                 : "r"(a0), "r"(a1), "r"(a2), "r"(a3), "r"(b0), "r"(b1))

// =================== tf32 mma.sync NT GEMM (unchanged from R4) ===============
#define GSTAGES 4
#define ASTRIDE 36
#define ATILE_WORDS (128 * ASTRIDE)
#define STAGE_BYTES (2 * ATILE_WORDS * 4)
#define GEMM_SMEM (GSTAGES * STAGE_BYTES)

__global__ __launch_bounds__(256) void gemm_mma(
    const float* __restrict__ A, const float* __restrict__ W,
    const float* __restrict__ bias, float* __restrict__ C,
    int M, int N, int K)
{
    extern __shared__ float dynf[];
    const uint32_t smbase = smem_u32(dynf);

    const int bm = blockIdx.y * 128;
    const int bn = blockIdx.x * 128;
    const int tid = threadIdx.x;
    const int wid = tid >> 5;
    const int lane = tid & 31;
    const int g = lane >> 2;
    const int t = lane & 3;
    const int warp_m = wid >> 2;
    const int warp_n = wid & 3;
    const int mbase = warp_m * 64;
    const int nbase = warp_n * 32;
    const int lrow = ((lane >> 3) & 1) * 8 + (lane & 7);
    const int lcolb = (lane >> 4) * 16;

    const int nchunks = K / 32;

    const float* Abase = A + (size_t)bm * K;
    const float* Bbase = W + (size_t)bn * K;

    auto load_chunk = [&](int c, int s) {
        uint32_t sa = smbase + s * STAGE_BYTES;
        uint32_t sb = sa + ATILE_WORDS * 4;
        const float* Ap = Abase + c * 32;
        const float* Bp = Bbase + c * 32;
#pragma unroll
        for (int v = 0; v < 4; v++) {
            int idx = tid + 256 * v;
            int row = idx >> 3;
            int seg = idx & 7;
            uint32_t off = (uint32_t)(row * ASTRIDE + seg * 4) * 4;
            CP_ASYNC16(sa + off, Ap + (size_t)row * K + seg * 4);
            CP_ASYNC16(sb + off, Bp + (size_t)row * K + seg * 4);
        }
    };

    float c[4][4][4];
#pragma unroll
    for (int mt = 0; mt < 4; mt++)
#pragma unroll
        for (int nt = 0; nt < 4; nt++)
#pragma unroll
            for (int r = 0; r < 4; r++) c[mt][nt][r] = 0.f;

    for (int cc = 0; cc < GSTAGES - 1; cc++) {
        load_chunk(cc, cc);
        CP_COMMIT();
    }

    for (int i = 0; i < nchunks; i++) {
        const int s = i & (GSTAGES - 1);
        CP_WAIT2();
        __syncthreads();

        const int nxt = i + GSTAGES - 1;
        if (nxt < nchunks) load_chunk(nxt, nxt & (GSTAGES - 1));
        CP_COMMIT();

        const uint32_t sa = smbase + s * STAGE_BYTES;
        const float* Bs = dynf + s * (STAGE_BYTES / 4) + ATILE_WORDS;

#pragma unroll
        for (int ks = 0; ks < 4; ks++) {
            uint32_t a[4][4];
#pragma unroll
            for (int mt = 0; mt < 4; mt++) {
                uint32_t addr = sa +
                    (uint32_t)((mbase + mt * 16 + lrow) * ASTRIDE + ks * 8) * 4 + lcolb;
                LDSM_X4(a[mt][0], a[mt][1], a[mt][2], a[mt][3], addr);
            }
            uint32_t b[4][2];
#pragma unroll
            for (int nt = 0; nt < 4; nt++) {
                const float* bp = Bs + (nbase + nt * 8 + g) * ASTRIDE + ks * 8 + t;
                b[nt][0] = f2tf32(bp[0]);
                b[nt][1] = f2tf32(bp[4]);
            }
#pragma unroll
            for (int mt = 0; mt < 4; mt++)
#pragma unroll
                for (int r = 0; r < 4; r++)
                    a[mt][r] = f2tf32(__uint_as_float(a[mt][r]));
#pragma unroll
            for (int mt = 0; mt < 4; mt++)
#pragma unroll
                for (int nt = 0; nt < 4; nt++)
                    MMA_TF32(c[mt][nt], a[mt], b[nt]);
        }
    }

#pragma unroll
    for (int mt = 0; mt < 4; mt++) {
        const int r0 = bm + mbase + mt * 16 + g;
#pragma unroll
        for (int nt = 0; nt < 4; nt++) {
            const int col = bn + nbase + nt * 8 + 2 * t;
            const float b0 = bias[col], b1 = bias[col + 1];
            float2 o0 = make_float2(c[mt][nt][0] + b0, c[mt][nt][1] + b1);
            float2 o1 = make_float2(c[mt][nt][2] + b0, c[mt][nt][3] + b1);
            *(float2*)&C[(size_t)r0 * N + col] = o0;
            *(float2*)&C[(size_t)(r0 + 8) * N + col] = o1;
        }
    }
}

// =================== tensor-core attention ===================================
// Per CTA: (b, h, 128 q-rows). 8 warps x 16 q-rows. Key tiles of 128.
//  Phase1: S = Q @ K^T (tf32 mma); exp(S/8)*pol in registers; rowsum.
//  Phase2: O += P @ V with P register fragments (slot-permuted), V rows 2t/2t+1.
#define AQT 128
#define AKT 128
#define QSTR 76
#define KSTR 68
#define VSTR 68
#define QWORDS (AQT * QSTR)            // 9728
#define KVWORDS (AKT * KSTR)           // 8704
#define STAGEW (2 * KVWORDS)           // 17408
#define ATTN_SMEM ((QWORDS + 2 * STAGEW + SLEN) * 4)  // 182272 B

__global__ __launch_bounds__(256) void attn_tc(
    const float* __restrict__ Q, const float* __restrict__ K,
    const float* __restrict__ V, const float* __restrict__ pol,
    float* __restrict__ X)
{
    extern __shared__ float sf[];
    const uint32_t smbase = smem_u32(sf);

    const int qt = blockIdx.x;
    const int h  = blockIdx.y;
    const int b  = blockIdx.z;
    const int tid = threadIdx.x;
    const int wid = tid >> 5;
    const int lane = tid & 31;
    const int g = lane >> 2;
    const int t = lane & 3;
    const int lrow = ((lane >> 3) & 1) * 8 + (lane & 7);
    const int lcolb = (lane >> 4) * 16;

    const float* Qg = Q + ((size_t)(b * SLEN + qt * AQT)) * DMODEL + h * DK;
    const float* Kg = K + ((size_t)b * SLEN) * DMODEL + h * DK;
    const float* Vg = V + ((size_t)b * SLEN) * DMODEL + h * DK;
    const float* pg = pol + (size_t)b * SLEN;

    // group 0: Q tile + full policy row + KV tile 0
    {
#pragma unroll
        for (int v = 0; v < 8; v++) {
            int idx = tid + 256 * v;        // 0..2047
            int row = idx >> 4;
            int seg = idx & 15;
            CP_ASYNC16(smbase + (uint32_t)(row * QSTR + seg * 4) * 4,
                       Qg + (size_t)row * DMODEL + seg * 4);
        }
        CP_ASYNC16(smbase + (uint32_t)(QWORDS + 2 * STAGEW + tid * 4) * 4,
                   pg + tid * 4);
    }
    auto load_kv = [&](int kt, int s) {
        uint32_t kb = smbase + (uint32_t)(QWORDS + s * STAGEW) * 4;
        uint32_t vb = kb + KVWORDS * 4;
        const float* Kp = Kg + (size_t)(kt * AKT) * DMODEL;
        const float* Vp = Vg + (size_t)(kt * AKT) * DMODEL;
#pragma unroll
        for (int v = 0; v < 8; v++) {
            int idx = tid + 256 * v;
            int row = idx >> 4;
            int seg = idx & 15;
            uint32_t off = (uint32_t)(row * KSTR + seg * 4) * 4;
            CP_ASYNC16(kb + off, Kp + (size_t)row * DMODEL + seg * 4);
            CP_ASYNC16(vb + off, Vp + (size_t)row * DMODEL + seg * 4);
        }
    };
    load_kv(0, 0); CP_COMMIT();
    load_kv(1, 1); CP_COMMIT();

    uint32_t aq[8][4];          // Q fragments (tf32), hoisted across key tiles
    float O[8][4];
    float rs0 = 0.f, rs1 = 0.f;
#pragma unroll
    for (int n2 = 0; n2 < 8; n2++)
#pragma unroll
        for (int r = 0; r < 4; r++) O[n2][r] = 0.f;

    const int ntiles = SLEN / AKT;  // 8
    for (int kt = 0; kt < ntiles; kt++) {
        const int s = kt & 1;
        CP_WAIT1();
        __syncthreads();

        if (kt == 0) {
#pragma unroll
            for (int ks = 0; ks < 8; ks++) {
                uint32_t addr = smbase +
                    (uint32_t)((wid * 16 + lrow) * QSTR + ks * 8) * 4 + lcolb;
                LDSM_X4(aq[ks][0], aq[ks][1], aq[ks][2], aq[ks][3], addr);
            }
#pragma unroll
            for (int ks = 0; ks < 8; ks++)
#pragma unroll
                for (int r = 0; r < 4; r++)
                    aq[ks][r] = f2tf32(__uint_as_float(aq[ks][r]));
        }

        const float* Ksf = sf + QWORDS + s * STAGEW;
        const float* Vsf = Ksf + KVWORDS;

        // ---- phase 1: S = Q K^T ----
        float sc[16][4];
#pragma unroll
        for (int nt = 0; nt < 16; nt++)
#pragma unroll
            for (int r = 0; r < 4; r++) sc[nt][r] = 0.f;

#pragma unroll
        for (int ks = 0; ks < 8; ks++) {
#pragma unroll
            for (int nt = 0; nt < 16; nt++) {
                const float* bp = Ksf + (nt * 8 + g) * KSTR + ks * 8 + t;
                uint32_t b0 = f2tf32(bp[0]);
                uint32_t b1 = f2tf32(bp[4]);
                MMA_TF32_4(sc[nt], aq[ks][0], aq[ks][1], aq[ks][2], aq[ks][3], b0, b1);
            }
        }

        // ---- exp(S/8)*pol, rowsum, convert P to tf32 in place ----
        const float* pk = sf + QWORDS + 2 * STAGEW + kt * AKT;
#pragma unroll
        for (int nt = 0; nt < 16; nt++) {
            float p0 = pk[nt * 8 + 2 * t];
            float p1 = pk[nt * 8 + 2 * t + 1];
            float e0 = __expf(sc[nt][0] * 0.125f) * p0;
            float e1 = __expf(sc[nt][1] * 0.125f) * p1;
            float e2 = __expf(sc[nt][2] * 0.125f) * p0;
            float e3 = __expf(sc[nt][3] * 0.125f) * p1;
            rs0 += e0 + e1;
            rs1 += e2 + e3;
            sc[nt][0] = __uint_as_float(f2tf32(e0));
            sc[nt][1] = __uint_as_float(f2tf32(e1));
            sc[nt][2] = __uint_as_float(f2tf32(e2));
            sc[nt][3] = __uint_as_float(f2tf32(e3));
        }

        // ---- phase 2: O += P V.  A slots = {c0, c2, c1, c3}; V rows 2t, 2t+1.
#pragma unroll
        for (int k2 = 0; k2 < 16; k2++) {
            const float* vrow = Vsf + (k2 * 8 + 2 * t) * VSTR;
            uint32_t pa0 = __float_as_uint(sc[k2][0]);
            uint32_t pa1 = __float_as_uint(sc[k2][2]);
            uint32_t pa2 = __float_as_uint(sc[k2][1]);
            uint32_t pa3 = __float_as_uint(sc[k2][3]);
#pragma unroll
            for (int n2 = 0; n2 < 8; n2++) {
                uint32_t b0 = f2tf32(vrow[n2 * 8 + g]);
                uint32_t b1 = f2tf32(vrow[VSTR + n2 * 8 + g]);
                MMA_TF32_4(O[n2], pa0, pa1, pa2, pa3, b0, b1);
            }
        }

        __syncthreads();
        if (kt + 2 < ntiles) load_kv(kt + 2, s);
        CP_COMMIT();
    }

    // quad-reduce rowsums (lanes differing only in t)
    rs0 += __shfl_xor_sync(0xffffffffu, rs0, 1);
    rs0 += __shfl_xor_sync(0xffffffffu, rs0, 2);
    rs1 += __shfl_xor_sync(0xffffffffu, rs1, 1);
    rs1 += __shfl_xor_sync(0xffffffffu, rs1, 2);
    const float i0 = 1.f / (rs0 + 1e-6f);
    const float i1 = 1.f / (rs1 + 1e-6f);

    float* Xg = X + ((size_t)(b * SLEN + qt * AQT + wid * 16)) * DMODEL + h * DK;
#pragma unroll
    for (int n2 = 0; n2 < 8; n2++) {
        int col = n2 * 8 + 2 * t;
        float2 o0 = make_float2(O[n2][0] * i0, O[n2][1] * i0);
        float2 o1 = make_float2(O[n2][2] * i1, O[n2][3] * i1);
        *(float2*)&Xg[(size_t)g * DMODEL + col] = o0;
        *(float2*)&Xg[(size_t)(g + 8) * DMODEL + col] = o1;
    }
}

// ---------------- launch ------------------------------------------------------
extern "C" void kernel_launch(void* const* d_in, const int* in_sizes, int n_in,
                              void* d_out, int out_size)
{
    const float* query   = (const float*)d_in[0];
    const float* key     = (const float*)d_in[1];
    const float* value   = (const float*)d_in[2];
    const float* policy  = (const float*)d_in[3];
    const float* wq_w    = (const float*)d_in[4];
    const float* wq_b    = (const float*)d_in[5];
    const float* wk_w    = (const float*)d_in[6];
    const float* wk_b    = (const float*)d_in[7];
    const float* wv_w    = (const float*)d_in[8];
    const float* wv_b    = (const float*)d_in[9];
    const float* dense_w = (const float*)d_in[10];
    const float* dense_b = (const float*)d_in[11];
    float* out = (float*)d_out;

    float *Qp, *Kp, *Vp, *Xp;
    cudaGetSymbolAddress((void**)&Qp, g_Q);
    cudaGetSymbolAddress((void**)&Kp, g_K);
    cudaGetSymbolAddress((void**)&Vp, g_V);
    cudaGetSymbolAddress((void**)&Xp, g_X);

    cudaFuncSetAttribute(gemm_mma, cudaFuncAttributeMaxDynamicSharedMemorySize, GEMM_SMEM);
    cudaFuncSetAttribute(attn_tc, cudaFuncAttributeMaxDynamicSharedMemorySize, ATTN_SMEM);

    dim3 gblk(DMODEL / 128, MROWS / 128);  // (8, 64)
    gemm_mma<<<gblk, 256, GEMM_SMEM>>>(query, wq_w, wq_b, Qp, MROWS, DMODEL, DMODEL);
    gemm_mma<<<gblk, 256, GEMM_SMEM>>>(key,   wk_w, wk_b, Kp, MROWS, DMODEL, DMODEL);
    gemm_mma<<<gblk, 256, GEMM_SMEM>>>(value, wv_w, wv_b, Vp, MROWS, DMODEL, DMODEL);

    dim3 gattn(SLEN / AQT, NHEADS, BATCH);  // (8, 16, 8)
    attn_tc<<<gattn, 256, ATTN_SMEM>>>(Qp, Kp, Vp, policy, Xp);

    gemm_mma<<<gblk, 256, GEMM_SMEM>>>(Xp, dense_w, dense_b, out, MROWS, DMODEL, DMODEL);
}

// round 10
// speedup vs baseline: 3.2380x; 1.0529x over previous
#include <cuda_runtime.h>
#include <cuda_bf16.h>
#include <cstdint>
#include <cstddef>

// Problem constants
#define BATCH 8
#define SLEN 1024
#define DMODEL 1024
#define NHEADS 16
#define DK 64
#define MROWS (BATCH * SLEN)   // 8192

// ---------------- scratch (device globals; no allocation allowed) ------------
__device__ float g_Q[MROWS * DMODEL];
__device__ float g_K[MROWS * DMODEL];
__device__ float g_V[MROWS * DMODEL];
__device__ float g_X[MROWS * DMODEL];

// =================== PTX helpers =============================================
static __device__ __forceinline__ uint32_t smem_u32(const void* p) {
    uint32_t a;
    asm("{ .reg .u64 t; cvta.to.shared.u64 t, %1; cvt.u32.u64 %0, t; }"
        : "=r"(a) : "l"(p));
    return a;
}

#define CP_ASYNC16(dst, src) \
    asm volatile("cp.async.cg.shared.global [%0], [%1], 16;" \
                 :: "r"(dst), "l"(src) : "memory")
#define CP_COMMIT() asm volatile("cp.async.commit_group;" ::: "memory")
#define CP_WAIT2()  asm volatile("cp.async.wait_group 2;" ::: "memory")
#define CP_WAIT1()  asm volatile("cp.async.wait_group 1;" ::: "memory")

static __device__ __forceinline__ uint32_t f2tf32(float x) {
    uint32_t r;
    asm("cvt.rna.tf32.f32 %0, %1;" : "=r"(r) : "f"(x));
    return r;
}

#define LDSM_X4(r0, r1, r2, r3, addr) \
    asm volatile("ldmatrix.sync.aligned.m8n8.x4.shared.b16 {%0,%1,%2,%3}, [%4];" \
                 : "=r"(r0), "=r"(r1), "=r"(r2), "=r"(r3) : "r"(addr))

#define MMA_TF32(c, a, b) \
    asm volatile("mma.sync.aligned.m16n8k8.row.col.f32.tf32.tf32.f32 " \
                 "{%0,%1,%2,%3}, {%4,%5,%6,%7}, {%8,%9}, {%0,%1,%2,%3};" \
                 : "+f"((c)[0]), "+f"((c)[1]), "+f"((c)[2]), "+f"((c)[3]) \
                 : "r"((a)[0]), "r"((a)[1]), "r"((a)[2]), "r"((a)[3]), \
                   "r"((b)[0]), "r"((b)[1]))

#define MMA_TF32_4(c, a0, a1, a2, a3, b0, b1) \
    asm volatile("mma.sync.aligned.m16n8k8.row.col.f32.tf32.tf32.f32 " \
                 "{%0,%1,%2,%3}, {%4,%5,%6,%7}, {%8,%9}, {%0,%1,%2,%3};" \
                 : "+f"((c)[0]), "+f"((c)[1]), "+f"((c)[2]), "+f"((c)[3]) \
                 : "r"(a0), "r"(a1), "r"(a2), "r"(a3), "r"(b0), "r"(b1))

// =================== tf32 mma.sync NT GEMM body ==============================
// C[M,N] = A[M,K] @ W[N,K]^T + bias.  CTA 128x128, BK=32, 4-stage cp.async.
#define GSTAGES 4
#define ASTRIDE 36
#define ATILE_WORDS (128 * ASTRIDE)
#define STAGE_BYTES (2 * ATILE_WORDS * 4)
#define GEMM_SMEM (GSTAGES * STAGE_BYTES)

static __device__ __forceinline__ void gemm_body(
    float* dynf,
    const float* __restrict__ A, const float* __restrict__ W,
    const float* __restrict__ bias, float* __restrict__ C,
    int M, int N, int K, int bm, int bn)
{
    const uint32_t smbase = smem_u32(dynf);
    const int tid = threadIdx.x;
    const int wid = tid >> 5;
    const int lane = tid & 31;
    const int g = lane >> 2;
    const int t = lane & 3;
    const int warp_m = wid >> 2;
    const int warp_n = wid & 3;
    const int mbase = warp_m * 64;
    const int nbase = warp_n * 32;
    const int lrow = ((lane >> 3) & 1) * 8 + (lane & 7);
    const int lcolb = (lane >> 4) * 16;

    const int nchunks = K / 32;

    const float* Abase = A + (size_t)bm * K;
    const float* Bbase = W + (size_t)bn * K;

    auto load_chunk = [&](int c, int s) {
        uint32_t sa = smbase + s * STAGE_BYTES;
        uint32_t sb = sa + ATILE_WORDS * 4;
        const float* Ap = Abase + c * 32;
        const float* Bp = Bbase + c * 32;
#pragma unroll
        for (int v = 0; v < 4; v++) {
            int idx = tid + 256 * v;
            int row = idx >> 3;
            int seg = idx & 7;
            uint32_t off = (uint32_t)(row * ASTRIDE + seg * 4) * 4;
            CP_ASYNC16(sa + off, Ap + (size_t)row * K + seg * 4);
            CP_ASYNC16(sb + off, Bp + (size_t)row * K + seg * 4);
        }
    };

    float c[4][4][4];
#pragma unroll
    for (int mt = 0; mt < 4; mt++)
#pragma unroll
        for (int nt = 0; nt < 4; nt++)
#pragma unroll
            for (int r = 0; r < 4; r++) c[mt][nt][r] = 0.f;

    for (int cc = 0; cc < GSTAGES - 1; cc++) {
        load_chunk(cc, cc);
        CP_COMMIT();
    }

    for (int i = 0; i < nchunks; i++) {
        const int s = i & (GSTAGES - 1);
        CP_WAIT2();
        __syncthreads();

        const int nxt = i + GSTAGES - 1;
        if (nxt < nchunks) load_chunk(nxt, nxt & (GSTAGES - 1));
        CP_COMMIT();

        const uint32_t sa = smbase + s * STAGE_BYTES;
        const float* Bs = dynf + s * (STAGE_BYTES / 4) + ATILE_WORDS;

#pragma unroll
        for (int ks = 0; ks < 4; ks++) {
            uint32_t a[4][4];
#pragma unroll
            for (int mt = 0; mt < 4; mt++) {
                uint32_t addr = sa +
                    (uint32_t)((mbase + mt * 16 + lrow) * ASTRIDE + ks * 8) * 4 + lcolb;
                LDSM_X4(a[mt][0], a[mt][1], a[mt][2], a[mt][3], addr);
            }
            uint32_t b[4][2];
#pragma unroll
            for (int nt = 0; nt < 4; nt++) {
                const float* bp = Bs + (nbase + nt * 8 + g) * ASTRIDE + ks * 8 + t;
                b[nt][0] = f2tf32(bp[0]);
                b[nt][1] = f2tf32(bp[4]);
            }
#pragma unroll
            for (int mt = 0; mt < 4; mt++)
#pragma unroll
                for (int r = 0; r < 4; r++)
                    a[mt][r] = f2tf32(__uint_as_float(a[mt][r]));
#pragma unroll
            for (int mt = 0; mt < 4; mt++)
#pragma unroll
                for (int nt = 0; nt < 4; nt++)
                    MMA_TF32(c[mt][nt], a[mt], b[nt]);
        }
    }

#pragma unroll
    for (int mt = 0; mt < 4; mt++) {
        const int r0 = bm + mbase + mt * 16 + g;
#pragma unroll
        for (int nt = 0; nt < 4; nt++) {
            const int col = bn + nbase + nt * 8 + 2 * t;
            const float b0 = bias[col], b1 = bias[col + 1];
            float2 o0 = make_float2(c[mt][nt][0] + b0, c[mt][nt][1] + b1);
            float2 o1 = make_float2(c[mt][nt][2] + b0, c[mt][nt][3] + b1);
            *(float2*)&C[(size_t)r0 * N + col] = o0;
            *(float2*)&C[(size_t)(r0 + 8) * N + col] = o1;
        }
    }
}

__global__ __launch_bounds__(256) void gemm_mma(
    const float* __restrict__ A, const float* __restrict__ W,
    const float* __restrict__ bias, float* __restrict__ C,
    int M, int N, int K)
{
    extern __shared__ float dynf[];
    gemm_body(dynf, A, W, bias, C, M, N, K, blockIdx.y * 128, blockIdx.x * 128);
}

// merged Q/K/V projection: blockIdx.z selects (input, weight, bias, output)
__global__ __launch_bounds__(256) void qkv_mma(
    const float* __restrict__ Aq, const float* __restrict__ Ak, const float* __restrict__ Av,
    const float* __restrict__ Wq, const float* __restrict__ Wk, const float* __restrict__ Wv,
    const float* __restrict__ bq, const float* __restrict__ bk, const float* __restrict__ bv,
    float* __restrict__ Cq, float* __restrict__ Ck, float* __restrict__ Cv)
{
    extern __shared__ float dynf[];
    const float* A; const float* W; const float* bias; float* C;
    if (blockIdx.z == 0)      { A = Aq; W = Wq; bias = bq; C = Cq; }
    else if (blockIdx.z == 1) { A = Ak; W = Wk; bias = bk; C = Ck; }
    else                      { A = Av; W = Wv; bias = bv; C = Cv; }
    gemm_body(dynf, A, W, bias, C, MROWS, DMODEL, DMODEL,
              blockIdx.y * 128, blockIdx.x * 128);
}

// =================== tensor-core attention ===================================
// Per CTA: (b, h, 128 q-rows). 8 warps x 16 q-rows. Key tiles of 64.
// 2 CTAs/SM (regs capped via launch_bounds, smem 110KB).
#define AQT 128
#define AKT 64
#define QSTR 76
#define KSTR 68
#define VSTR 68
#define QWORDS (AQT * QSTR)            // 9728
#define KVWORDS (AKT * KSTR)           // 4352
#define STAGEW (2 * KVWORDS)           // 8704
#define ATTN_SMEM ((QWORDS + 2 * STAGEW + SLEN) * 4)  // 112640 B

__global__ __launch_bounds__(256, 2) void attn_tc(
    const float* __restrict__ Q, const float* __restrict__ K,
    const float* __restrict__ V, const float* __restrict__ pol,
    float* __restrict__ X)
{
    extern __shared__ float sf[];
    const uint32_t smbase = smem_u32(sf);

    const int qt = blockIdx.x;
    const int h  = blockIdx.y;
    const int b  = blockIdx.z;
    const int tid = threadIdx.x;
    const int wid = tid >> 5;
    const int lane = tid & 31;
    const int g = lane >> 2;
    const int t = lane & 3;
    const int lrow = ((lane >> 3) & 1) * 8 + (lane & 7);
    const int lcolb = (lane >> 4) * 16;

    const float* Qg = Q + ((size_t)(b * SLEN + qt * AQT)) * DMODEL + h * DK;
    const float* Kg = K + ((size_t)b * SLEN) * DMODEL + h * DK;
    const float* Vg = V + ((size_t)b * SLEN) * DMODEL + h * DK;
    const float* pg = pol + (size_t)b * SLEN;

    // group 0: Q tile + full policy row + KV tile 0
    {
#pragma unroll
        for (int v = 0; v < 8; v++) {
            int idx = tid + 256 * v;        // 0..2047
            int row = idx >> 4;
            int seg = idx & 15;
            CP_ASYNC16(smbase + (uint32_t)(row * QSTR + seg * 4) * 4,
                       Qg + (size_t)row * DMODEL + seg * 4);
        }
        CP_ASYNC16(smbase + (uint32_t)(QWORDS + 2 * STAGEW + tid * 4) * 4,
                   pg + tid * 4);
    }
    auto load_kv = [&](int kt, int s) {
        uint32_t kb = smbase + (uint32_t)(QWORDS + s * STAGEW) * 4;
        uint32_t vb = kb + KVWORDS * 4;
        const float* Kp = Kg + (size_t)(kt * AKT) * DMODEL;
        const float* Vp = Vg + (size_t)(kt * AKT) * DMODEL;
#pragma unroll
        for (int v = 0; v < 4; v++) {
            int idx = tid + 256 * v;        // 0..1023
            int row = idx >> 4;             // 0..63
            int seg = idx & 15;
            uint32_t off = (uint32_t)(row * KSTR + seg * 4) * 4;
            CP_ASYNC16(kb + off, Kp + (size_t)row * DMODEL + seg * 4);
            CP_ASYNC16(vb + off, Vp + (size_t)row * DMODEL + seg * 4);
        }
    };
    load_kv(0, 0); CP_COMMIT();
    load_kv(1, 1); CP_COMMIT();

    uint32_t aq[8][4];          // Q fragments (tf32), hoisted across key tiles
    float O[8][4];
    float rs0 = 0.f, rs1 = 0.f;
#pragma unroll
    for (int n2 = 0; n2 < 8; n2++)
#pragma unroll
        for (int r = 0; r < 4; r++) O[n2][r] = 0.f;

    const int ntiles = SLEN / AKT;  // 16
    for (int kt = 0; kt < ntiles; kt++) {
        const int s = kt & 1;
        CP_WAIT1();
        __syncthreads();

        if (kt == 0) {
#pragma unroll
            for (int ks = 0; ks < 8; ks++) {
                uint32_t addr = smbase +
                    (uint32_t)((wid * 16 + lrow) * QSTR + ks * 8) * 4 + lcolb;
                LDSM_X4(aq[ks][0], aq[ks][1], aq[ks][2], aq[ks][3], addr);
            }
#pragma unroll
            for (int ks = 0; ks < 8; ks++)
#pragma unroll
                for (int r = 0; r < 4; r++)
                    aq[ks][r] = f2tf32(__uint_as_float(aq[ks][r]));
        }

        const float* Ksf = sf + QWORDS + s * STAGEW;
        const float* Vsf = Ksf + KVWORDS;

        // ---- phase 1: S = Q K^T (64 keys) ----
        float sc[8][4];
#pragma unroll
        for (int nt = 0; nt < 8; nt++)
#pragma unroll
            for (int r = 0; r < 4; r++) sc[nt][r] = 0.f;

#pragma unroll
        for (int ks = 0; ks < 8; ks++) {
#pragma unroll
            for (int nt = 0; nt < 8; nt++) {
                const float* bp = Ksf + (nt * 8 + g) * KSTR + ks * 8 + t;
                uint32_t b0 = f2tf32(bp[0]);
                uint32_t b1 = f2tf32(bp[4]);
                MMA_TF32_4(sc[nt], aq[ks][0], aq[ks][1], aq[ks][2], aq[ks][3], b0, b1);
            }
        }

        // ---- exp(S/8)*pol, rowsum, convert P to tf32 in place ----
        const float* pk = sf + QWORDS + 2 * STAGEW + kt * AKT;
#pragma unroll
        for (int nt = 0; nt < 8; nt++) {
            float p0 = pk[nt * 8 + 2 * t];
            float p1 = pk[nt * 8 + 2 * t + 1];
            float e0 = __expf(sc[nt][0] * 0.125f) * p0;
            float e1 = __expf(sc[nt][1] * 0.125f) * p1;
            float e2 = __expf(sc[nt][2] * 0.125f) * p0;
            float e3 = __expf(sc[nt][3] * 0.125f) * p1;
            rs0 += e0 + e1;
            rs1 += e2 + e3;
            sc[nt][0] = __uint_as_float(f2tf32(e0));
            sc[nt][1] = __uint_as_float(f2tf32(e1));
            sc[nt][2] = __uint_as_float(f2tf32(e2));
            sc[nt][3] = __uint_as_float(f2tf32(e3));
        }

        // ---- phase 2: O += P V.  A slots = {c0, c2, c1, c3}; V rows 2t, 2t+1.
#pragma unroll
        for (int k2 = 0; k2 < 8; k2++) {
            const float* vrow = Vsf + (k2 * 8 + 2 * t) * VSTR;
            uint32_t pa0 = __float_as_uint(sc[k2][0]);
            uint32_t pa1 = __float_as_uint(sc[k2][2]);
            uint32_t pa2 = __float_as_uint(sc[k2][1]);
            uint32_t pa3 = __float_as_uint(sc[k2][3]);
#pragma unroll
            for (int n2 = 0; n2 < 8; n2++) {
                uint32_t b0 = f2tf32(vrow[n2 * 8 + g]);
                uint32_t b1 = f2tf32(vrow[VSTR + n2 * 8 + g]);
                MMA_TF32_4(O[n2], pa0, pa1, pa2, pa3, b0, b1);
            }
        }

        __syncthreads();
        if (kt + 2 < ntiles) load_kv(kt + 2, s);
        CP_COMMIT();
    }

    // quad-reduce rowsums (lanes differing only in t)
    rs0 += __shfl_xor_sync(0xffffffffu, rs0, 1);
    rs0 += __shfl_xor_sync(0xffffffffu, rs0, 2);
    rs1 += __shfl_xor_sync(0xffffffffu, rs1, 1);
    rs1 += __shfl_xor_sync(0xffffffffu, rs1, 2);
    const float i0 = 1.f / (rs0 + 1e-6f);
    const float i1 = 1.f / (rs1 + 1e-6f);

    float* Xg = X + ((size_t)(b * SLEN + qt * AQT + wid * 16)) * DMODEL + h * DK;
#pragma unroll
    for (int n2 = 0; n2 < 8; n2++) {
        int col = n2 * 8 + 2 * t;
        float2 o0 = make_float2(O[n2][0] * i0, O[n2][1] * i0);
        float2 o1 = make_float2(O[n2][2] * i1, O[n2][3] * i1);
        *(float2*)&Xg[(size_t)g * DMODEL + col] = o0;
        *(float2*)&Xg[(size_t)(g + 8) * DMODEL + col] = o1;
    }
}

// ---------------- launch ------------------------------------------------------
extern "C" void kernel_launch(void* const* d_in, const int* in_sizes, int n_in,
                              void* d_out, int out_size)
{
    const float* query   = (const float*)d_in[0];
    const float* key     = (const float*)d_in[1];
    const float* value   = (const float*)d_in[2];
    const float* policy  = (const float*)d_in[3];
    const float* wq_w    = (const float*)d_in[4];
    const float* wq_b    = (const float*)d_in[5];
    const float* wk_w    = (const float*)d_in[6];
    const float* wk_b    = (const float*)d_in[7];
    const float* wv_w    = (const float*)d_in[8];
    const float* wv_b    = (const float*)d_in[9];
    const float* dense_w = (const float*)d_in[10];
    const float* dense_b = (const float*)d_in[11];
    float* out = (float*)d_out;

    float *Qp, *Kp, *Vp, *Xp;
    cudaGetSymbolAddress((void**)&Qp, g_Q);
    cudaGetSymbolAddress((void**)&Kp, g_K);
    cudaGetSymbolAddress((void**)&Vp, g_V);
    cudaGetSymbolAddress((void**)&Xp, g_X);

    cudaFuncSetAttribute(gemm_mma, cudaFuncAttributeMaxDynamicSharedMemorySize, GEMM_SMEM);
    cudaFuncSetAttribute(qkv_mma,  cudaFuncAttributeMaxDynamicSharedMemorySize, GEMM_SMEM);
    cudaFuncSetAttribute(attn_tc,  cudaFuncAttributeMaxDynamicSharedMemorySize, ATTN_SMEM);

    dim3 gqkv(DMODEL / 128, MROWS / 128, 3);  // (8, 64, 3)
    qkv_mma<<<gqkv, 256, GEMM_SMEM>>>(query, key, value,
                                      wq_w, wk_w, wv_w,
                                      wq_b, wk_b, wv_b,
                                      Qp, Kp, Vp);

    dim3 gattn(SLEN / AQT, NHEADS, BATCH);  // (8, 16, 8)
    attn_tc<<<gattn, 256, ATTN_SMEM>>>(Qp, Kp, Vp, policy, Xp);

    dim3 gblk(DMODEL / 128, MROWS / 128);  // (8, 64)
    gemm_mma<<<gblk, 256, GEMM_SMEM>>>(Xp, dense_w, dense_b, out, MROWS, DMODEL, DMODEL);
}

// round 12
// speedup vs baseline: 3.6650x; 1.1319x over previous
#include <cuda_runtime.h>
#include <cuda_bf16.h>
#include <cstdint>
#include <cstddef>

// Problem constants
#define BATCH 8
#define SLEN 1024
#define DMODEL 1024
#define NHEADS 16
#define DK 64
#define MROWS (BATCH * SLEN)   // 8192

// ---------------- scratch (device globals; no allocation allowed) ------------
__device__ float g_Q[MROWS * DMODEL];
__device__ float g_K[MROWS * DMODEL];
__device__ float g_V[MROWS * DMODEL];
__device__ float g_X[MROWS * DMODEL];

// =================== PTX helpers =============================================
static __device__ __forceinline__ uint32_t smem_u32(const void* p) {
    uint32_t a;
    asm("{ .reg .u64 t; cvta.to.shared.u64 t, %1; cvt.u32.u64 %0, t; }"
        : "=r"(a) : "l"(p));
    return a;
}

#define CP_ASYNC16(dst, src) \
    asm volatile("cp.async.cg.shared.global [%0], [%1], 16;" \
                 :: "r"(dst), "l"(src) : "memory")
#define CP_COMMIT() asm volatile("cp.async.commit_group;" ::: "memory")
#define CP_WAIT1()  asm volatile("cp.async.wait_group 1;" ::: "memory")

static __device__ __forceinline__ uint32_t f2tf32(float x) {
    uint32_t r;
    asm("cvt.rna.tf32.f32 %0, %1;" : "=r"(r) : "f"(x));
    return r;
}

#define LDSM_X4(r0, r1, r2, r3, addr) \
    asm volatile("ldmatrix.sync.aligned.m8n8.x4.shared.b16 {%0,%1,%2,%3}, [%4];" \
                 : "=r"(r0), "=r"(r1), "=r"(r2), "=r"(r3) : "r"(addr))

#define MMA_TF32(c, a, b) \
    asm volatile("mma.sync.aligned.m16n8k8.row.col.f32.tf32.tf32.f32 " \
                 "{%0,%1,%2,%3}, {%4,%5,%6,%7}, {%8,%9}, {%0,%1,%2,%3};" \
                 : "+f"((c)[0]), "+f"((c)[1]), "+f"((c)[2]), "+f"((c)[3]) \
                 : "r"((a)[0]), "r"((a)[1]), "r"((a)[2]), "r"((a)[3]), \
                   "r"((b)[0]), "r"((b)[1]))

#define MMA_TF32_4(c, a0, a1, a2, a3, b0, b1) \
    asm volatile("mma.sync.aligned.m16n8k8.row.col.f32.tf32.tf32.f32 " \
                 "{%0,%1,%2,%3}, {%4,%5,%6,%7}, {%8,%9}, {%0,%1,%2,%3};" \
                 : "+f"((c)[0]), "+f"((c)[1]), "+f"((c)[2]), "+f"((c)[3]) \
                 : "r"(a0), "r"(a1), "r"(a2), "r"(a3), "r"(b0), "r"(b1))

// =================== tf32 mma.sync NT GEMM body ==============================
// C[M,N] = A[M,K] @ W[N,K]^T + bias.  CTA 128x128, BK=32, 3-stage cp.async.
// 3 stages * 36864B = 110592B smem -> 2 CTAs/SM.
#define GSTAGES 3
#define ASTRIDE 36
#define ATILE_WORDS (128 * ASTRIDE)
#define STAGE_BYTES (2 * ATILE_WORDS * 4)
#define GEMM_SMEM (GSTAGES * STAGE_BYTES)   // 110592

static __device__ __forceinline__ void gemm_body(
    float* dynf,
    const float* __restrict__ A, const float* __restrict__ W,
    const float* __restrict__ bias, float* __restrict__ C,
    int M, int N, int K, int bm, int bn)
{
    const uint32_t smbase = smem_u32(dynf);
    const int tid = threadIdx.x;
    const int wid = tid >> 5;
    const int lane = tid & 31;
    const int g = lane >> 2;
    const int t = lane & 3;
    const int warp_m = wid >> 2;
    const int warp_n = wid & 3;
    const int mbase = warp_m * 64;
    const int nbase = warp_n * 32;
    const int lrow = ((lane >> 3) & 1) * 8 + (lane & 7);
    const int lcolb = (lane >> 4) * 16;

    const int nchunks = K / 32;

    const float* Abase = A + (size_t)bm * K;
    const float* Bbase = W + (size_t)bn * K;

    auto load_chunk = [&](int c, int s) {
        uint32_t sa = smbase + s * STAGE_BYTES;
        uint32_t sb = sa + ATILE_WORDS * 4;
        const float* Ap = Abase + c * 32;
        const float* Bp = Bbase + c * 32;
#pragma unroll
        for (int v = 0; v < 4; v++) {
            int idx = tid + 256 * v;
            int row = idx >> 3;
            int seg = idx & 7;
            uint32_t off = (uint32_t)(row * ASTRIDE + seg * 4) * 4;
            CP_ASYNC16(sa + off, Ap + (size_t)row * K + seg * 4);
            CP_ASYNC16(sb + off, Bp + (size_t)row * K + seg * 4);
        }
    };

    float c[4][4][4];
#pragma unroll
    for (int mt = 0; mt < 4; mt++)
#pragma unroll
        for (int nt = 0; nt < 4; nt++)
#pragma unroll
            for (int r = 0; r < 4; r++) c[mt][nt][r] = 0.f;

    // prologue: stages 0,1
    load_chunk(0, 0); CP_COMMIT();
    load_chunk(1, 1); CP_COMMIT();

    int s = 0;          // stage of chunk i
    int sl = 2;         // stage for chunk i+2
    for (int i = 0; i < nchunks; i++) {
        CP_WAIT1();
        __syncthreads();

        const int nxt = i + 2;
        if (nxt < nchunks) load_chunk(nxt, sl);
        CP_COMMIT();

        const uint32_t sa = smbase + s * STAGE_BYTES;
        const float* Bs = dynf + s * (STAGE_BYTES / 4) + ATILE_WORDS;

#pragma unroll
        for (int ks = 0; ks < 4; ks++) {
            uint32_t a[4][4];
#pragma unroll
            for (int mt = 0; mt < 4; mt++) {
                uint32_t addr = sa +
                    (uint32_t)((mbase + mt * 16 + lrow) * ASTRIDE + ks * 8) * 4 + lcolb;
                LDSM_X4(a[mt][0], a[mt][1], a[mt][2], a[mt][3], addr);
            }
            uint32_t b[4][2];
#pragma unroll
            for (int nt = 0; nt < 4; nt++) {
                const float* bp = Bs + (nbase + nt * 8 + g) * ASTRIDE + ks * 8 + t;
                b[nt][0] = f2tf32(bp[0]);
                b[nt][1] = f2tf32(bp[4]);
            }
#pragma unroll
            for (int mt = 0; mt < 4; mt++)
#pragma unroll
                for (int r = 0; r < 4; r++)
                    a[mt][r] = f2tf32(__uint_as_float(a[mt][r]));
#pragma unroll
            for (int mt = 0; mt < 4; mt++)
#pragma unroll
                for (int nt = 0; nt < 4; nt++)
                    MMA_TF32(c[mt][nt], a[mt], b[nt]);
        }

        s = (s == GSTAGES - 1) ? 0 : s + 1;
        sl = (sl == GSTAGES - 1) ? 0 : sl + 1;
    }

#pragma unroll
    for (int mt = 0; mt < 4; mt++) {
        const int r0 = bm + mbase + mt * 16 + g;
#pragma unroll
        for (int nt = 0; nt < 4; nt++) {
            const int col = bn + nbase + nt * 8 + 2 * t;
            const float b0 = bias[col], b1 = bias[col + 1];
            float2 o0 = make_float2(c[mt][nt][0] + b0, c[mt][nt][1] + b1);
            float2 o1 = make_float2(c[mt][nt][2] + b0, c[mt][nt][3] + b1);
            *(float2*)&C[(size_t)r0 * N + col] = o0;
            *(float2*)&C[(size_t)(r0 + 8) * N + col] = o1;
        }
    }
}

__global__ __launch_bounds__(256, 2) void gemm_mma(
    const float* __restrict__ A, const float* __restrict__ W,
    const float* __restrict__ bias, float* __restrict__ C,
    int M, int N, int K)
{
    extern __shared__ float dynf[];
    gemm_body(dynf, A, W, bias, C, M, N, K, blockIdx.y * 128, blockIdx.x * 128);
}

// merged Q/K/V projection: blockIdx.z selects (input, weight, bias, output)
__global__ __launch_bounds__(256, 2) void qkv_mma(
    const float* __restrict__ Aq, const float* __restrict__ Ak, const float* __restrict__ Av,
    const float* __restrict__ Wq, const float* __restrict__ Wk, const float* __restrict__ Wv,
    const float* __restrict__ bq, const float* __restrict__ bk, const float* __restrict__ bv,
    float* __restrict__ Cq, float* __restrict__ Ck, float* __restrict__ Cv)
{
    extern __shared__ float dynf[];
    const float* A; const float* W; const float* bias; float* C;
    if (blockIdx.z == 0)      { A = Aq; W = Wq; bias = bq; C = Cq; }
    else if (blockIdx.z == 1) { A = Ak; W = Wk; bias = bk; C = Ck; }
    else                      { A = Av; W = Wv; bias = bv; C = Cv; }
    gemm_body(dynf, A, W, bias, C, MROWS, DMODEL, DMODEL,
              blockIdx.y * 128, blockIdx.x * 128);
}

// =================== tensor-core attention (unchanged) =======================
#define AQT 128
#define AKT 64
#define QSTR 76
#define KSTR 68
#define VSTR 68
#define QWORDS (AQT * QSTR)            // 9728
#define KVWORDS (AKT * KSTR)           // 4352
#define STAGEW (2 * KVWORDS)           // 8704
#define ATTN_SMEM ((QWORDS + 2 * STAGEW + SLEN) * 4)  // 112640 B

__global__ __launch_bounds__(256, 2) void attn_tc(
    const float* __restrict__ Q, const float* __restrict__ K,
    const float* __restrict__ V, const float* __restrict__ pol,
    float* __restrict__ X)
{
    extern __shared__ float sf[];
    const uint32_t smbase = smem_u32(sf);

    const int qt = blockIdx.x;
    const int h  = blockIdx.y;
    const int b  = blockIdx.z;
    const int tid = threadIdx.x;
    const int wid = tid >> 5;
    const int lane = tid & 31;
    const int g = lane >> 2;
    const int t = lane & 3;
    const int lrow = ((lane >> 3) & 1) * 8 + (lane & 7);
    const int lcolb = (lane >> 4) * 16;

    const float* Qg = Q + ((size_t)(b * SLEN + qt * AQT)) * DMODEL + h * DK;
    const float* Kg = K + ((size_t)b * SLEN) * DMODEL + h * DK;
    const float* Vg = V + ((size_t)b * SLEN) * DMODEL + h * DK;
    const float* pg = pol + (size_t)b * SLEN;

    {
#pragma unroll
        for (int v = 0; v < 8; v++) {
            int idx = tid + 256 * v;
            int row = idx >> 4;
            int seg = idx & 15;
            CP_ASYNC16(smbase + (uint32_t)(row * QSTR + seg * 4) * 4,
                       Qg + (size_t)row * DMODEL + seg * 4);
        }
        CP_ASYNC16(smbase + (uint32_t)(QWORDS + 2 * STAGEW + tid * 4) * 4,
                   pg + tid * 4);
    }
    auto load_kv = [&](int kt, int s) {
        uint32_t kb = smbase + (uint32_t)(QWORDS + s * STAGEW) * 4;
        uint32_t vb = kb + KVWORDS * 4;
        const float* Kp = Kg + (size_t)(kt * AKT) * DMODEL;
        const float* Vp = Vg + (size_t)(kt * AKT) * DMODEL;
#pragma unroll
        for (int v = 0; v < 4; v++) {
            int idx = tid + 256 * v;
            int row = idx >> 4;
            int seg = idx & 15;
            uint32_t off = (uint32_t)(row * KSTR + seg * 4) * 4;
            CP_ASYNC16(kb + off, Kp + (size_t)row * DMODEL + seg * 4);
            CP_ASYNC16(vb + off, Vp + (size_t)row * DMODEL + seg * 4);
        }
    };
    load_kv(0, 0); CP_COMMIT();
    load_kv(1, 1); CP_COMMIT();

    uint32_t aq[8][4];
    float O[8][4];
    float rs0 = 0.f, rs1 = 0.f;
#pragma unroll
    for (int n2 = 0; n2 < 8; n2++)
#pragma unroll
        for (int r = 0; r < 4; r++) O[n2][r] = 0.f;

    const int ntiles = SLEN / AKT;  // 16
    for (int kt = 0; kt < ntiles; kt++) {
        const int s = kt & 1;
        CP_WAIT1();
        __syncthreads();

        if (kt == 0) {
#pragma unroll
            for (int ks = 0; ks < 8; ks++) {
                uint32_t addr = smbase +
                    (uint32_t)((wid * 16 + lrow) * QSTR + ks * 8) * 4 + lcolb;
                LDSM_X4(aq[ks][0], aq[ks][1], aq[ks][2], aq[ks][3], addr);
            }
#pragma unroll
            for (int ks = 0; ks < 8; ks++)
#pragma unroll
                for (int r = 0; r < 4; r++)
                    aq[ks][r] = f2tf32(__uint_as_float(aq[ks][r]));
        }

        const float* Ksf = sf + QWORDS + s * STAGEW;
        const float* Vsf = Ksf + KVWORDS;

        float sc[8][4];
#pragma unroll
        for (int nt = 0; nt < 8; nt++)
#pragma unroll
            for (int r = 0; r < 4; r++) sc[nt][r] = 0.f;

#pragma unroll
        for (int ks = 0; ks < 8; ks++) {
#pragma unroll
            for (int nt = 0; nt < 8; nt++) {
                const float* bp = Ksf + (nt * 8 + g) * KSTR + ks * 8 + t;
                uint32_t b0 = f2tf32(bp[0]);
                uint32_t b1 = f2tf32(bp[4]);
                MMA_TF32_4(sc[nt], aq[ks][0], aq[ks][1], aq[ks][2], aq[ks][3], b0, b1);
            }
        }

        const float* pk = sf + QWORDS + 2 * STAGEW + kt * AKT;
#pragma unroll
        for (int nt = 0; nt < 8; nt++) {
            float p0 = pk[nt * 8 + 2 * t];
            float p1 = pk[nt * 8 + 2 * t + 1];
            float e0 = __expf(sc[nt][0] * 0.125f) * p0;
            float e1 = __expf(sc[nt][1] * 0.125f) * p1;
            float e2 = __expf(sc[nt][2] * 0.125f) * p0;
            float e3 = __expf(sc[nt][3] * 0.125f) * p1;
            rs0 += e0 + e1;
            rs1 += e2 + e3;
            sc[nt][0] = __uint_as_float(f2tf32(e0));
            sc[nt][1] = __uint_as_float(f2tf32(e1));
            sc[nt][2] = __uint_as_float(f2tf32(e2));
            sc[nt][3] = __uint_as_float(f2tf32(e3));
        }

#pragma unroll
        for (int k2 = 0; k2 < 8; k2++) {
            const float* vrow = Vsf + (k2 * 8 + 2 * t) * VSTR;
            uint32_t pa0 = __float_as_uint(sc[k2][0]);
            uint32_t pa1 = __float_as_uint(sc[k2][2]);
            uint32_t pa2 = __float_as_uint(sc[k2][1]);
            uint32_t pa3 = __float_as_uint(sc[k2][3]);
#pragma unroll
            for (int n2 = 0; n2 < 8; n2++) {
                uint32_t b0 = f2tf32(vrow[n2 * 8 + g]);
                uint32_t b1 = f2tf32(vrow[VSTR + n2 * 8 + g]);
                MMA_TF32_4(O[n2], pa0, pa1, pa2, pa3, b0, b1);
            }
        }

        __syncthreads();
        if (kt + 2 < ntiles) load_kv(kt + 2, s);
        CP_COMMIT();
    }

    rs0 += __shfl_xor_sync(0xffffffffu, rs0, 1);
    rs0 += __shfl_xor_sync(0xffffffffu, rs0, 2);
    rs1 += __shfl_xor_sync(0xffffffffu, rs1, 1);
    rs1 += __shfl_xor_sync(0xffffffffu, rs1, 2);
    const float i0 = 1.f / (rs0 + 1e-6f);
    const float i1 = 1.f / (rs1 + 1e-6f);

    float* Xg = X + ((size_t)(b * SLEN + qt * AQT + wid * 16)) * DMODEL + h * DK;
#pragma unroll
    for (int n2 = 0; n2 < 8; n2++) {
        int col = n2 * 8 + 2 * t;
        float2 o0 = make_float2(O[n2][0] * i0, O[n2][1] * i0);
        float2 o1 = make_float2(O[n2][2] * i1, O[n2][3] * i1);
        *(float2*)&Xg[(size_t)g * DMODEL + col] = o0;
        *(float2*)&Xg[(size_t)(g + 8) * DMODEL + col] = o1;
    }
}

// ---------------- launch ------------------------------------------------------
extern "C" void kernel_launch(void* const* d_in, const int* in_sizes, int n_in,
                              void* d_out, int out_size)
{
    const float* query   = (const float*)d_in[0];
    const float* key     = (const float*)d_in[1];
    const float* value   = (const float*)d_in[2];
    const float* policy  = (const float*)d_in[3];
    const float* wq_w    = (const float*)d_in[4];
    const float* wq_b    = (const float*)d_in[5];
    const float* wk_w    = (const float*)d_in[6];
    const float* wk_b    = (const float*)d_in[7];
    const float* wv_w    = (const float*)d_in[8];
    const float* wv_b    = (const float*)d_in[9];
    const float* dense_w = (const float*)d_in[10];
    const float* dense_b = (const float*)d_in[11];
    float* out = (float*)d_out;

    float *Qp, *Kp, *Vp, *Xp;
    cudaGetSymbolAddress((void**)&Qp, g_Q);
    cudaGetSymbolAddress((void**)&Kp, g_K);
    cudaGetSymbolAddress((void**)&Vp, g_V);
    cudaGetSymbolAddress((void**)&Xp, g_X);

    cudaFuncSetAttribute(gemm_mma, cudaFuncAttributeMaxDynamicSharedMemorySize, GEMM_SMEM);
    cudaFuncSetAttribute(qkv_mma,  cudaFuncAttributeMaxDynamicSharedMemorySize, GEMM_SMEM);
    cudaFuncSetAttribute(attn_tc,  cudaFuncAttributeMaxDynamicSharedMemorySize, ATTN_SMEM);

    dim3 gqkv(DMODEL / 128, MROWS / 128, 3);  // (8, 64, 3)
    qkv_mma<<<gqkv, 256, GEMM_SMEM>>>(query, key, value,
                                      wq_w, wk_w, wv_w,
                                      wq_b, wk_b, wv_b,
                                      Qp, Kp, Vp);

    dim3 gattn(SLEN / AQT, NHEADS, BATCH);  // (8, 16, 8)
    attn_tc<<<gattn, 256, ATTN_SMEM>>>(Qp, Kp, Vp, policy, Xp);

    dim3 gblk(DMODEL / 128, MROWS / 128);  // (8, 64)
    gemm_mma<<<gblk, 256, GEMM_SMEM>>>(Xp, dense_w, dense_b, out, MROWS, DMODEL, DMODEL);
}

// round 14
// speedup vs baseline: 4.0769x; 1.1124x over previous
#include <cuda_runtime.h>
#include <cuda_bf16.h>
#include <cstdint>
#include <cstddef>

// Problem constants
#define BATCH 8
#define SLEN 1024
#define DMODEL 1024
#define NHEADS 16
#define DK 64
#define MROWS (BATCH * SLEN)   // 8192

// ---------------- scratch (device globals; no allocation allowed) ------------
__device__ float g_Q[MROWS * DMODEL];
__device__ float g_K[MROWS * DMODEL];
__device__ float g_V[MROWS * DMODEL];
__device__ float g_X[MROWS * DMODEL];
// tf32-pre-rounded copies
__device__ float g_Rq[MROWS * DMODEL];
__device__ float g_Rk[MROWS * DMODEL];
__device__ float g_Rv[MROWS * DMODEL];
__device__ float g_Rw[4 * DMODEL * DMODEL];   // wq, wk, wv, dense

// =================== PTX helpers =============================================
static __device__ __forceinline__ uint32_t smem_u32(const void* p) {
    uint32_t a;
    asm("{ .reg .u64 t; cvta.to.shared.u64 t, %1; cvt.u32.u64 %0, t; }"
        : "=r"(a) : "l"(p));
    return a;
}

#define CP_ASYNC16(dst, src) \
    asm volatile("cp.async.cg.shared.global [%0], [%1], 16;" \
                 :: "r"(dst), "l"(src) : "memory")
#define CP_COMMIT() asm volatile("cp.async.commit_group;" ::: "memory")
#define CP_WAIT1()  asm volatile("cp.async.wait_group 1;" ::: "memory")

static __device__ __forceinline__ uint32_t f2tf32(float x) {
    uint32_t r;
    asm("cvt.rna.tf32.f32 %0, %1;" : "=r"(r) : "f"(x));
    return r;
}
static __device__ __forceinline__ float rnd_tf32(float x) {
    return __uint_as_float(f2tf32(x));
}

#define LDSM_X4(r0, r1, r2, r3, addr) \
    asm volatile("ldmatrix.sync.aligned.m8n8.x4.shared.b16 {%0,%1,%2,%3}, [%4];" \
                 : "=r"(r0), "=r"(r1), "=r"(r2), "=r"(r3) : "r"(addr))

#define MMA_TF32(c, a, b) \
    asm volatile("mma.sync.aligned.m16n8k8.row.col.f32.tf32.tf32.f32 " \
                 "{%0,%1,%2,%3}, {%4,%5,%6,%7}, {%8,%9}, {%0,%1,%2,%3};" \
                 : "+f"((c)[0]), "+f"((c)[1]), "+f"((c)[2]), "+f"((c)[3]) \
                 : "r"((a)[0]), "r"((a)[1]), "r"((a)[2]), "r"((a)[3]), \
                   "r"((b)[0]), "r"((b)[1]))

#define MMA_TF32_4(c, a0, a1, a2, a3, b0, b1) \
    asm volatile("mma.sync.aligned.m16n8k8.row.col.f32.tf32.tf32.f32 " \
                 "{%0,%1,%2,%3}, {%4,%5,%6,%7}, {%8,%9}, {%0,%1,%2,%3};" \
                 : "+f"((c)[0]), "+f"((c)[1]), "+f"((c)[2]), "+f"((c)[3]) \
                 : "r"(a0), "r"(a1), "r"(a2), "r"(a3), "r"(b0), "r"(b1))

// =================== tf32 pre-round passes ===================================
// rounds fp32 -> tf32-representable fp32 (zeroed low mantissa), so MMA register
// truncation later is the identity. Numerically identical to per-use cvt.rna.
__global__ __launch_bounds__(256) void round_inputs(
    const float* __restrict__ q, const float* __restrict__ k,
    const float* __restrict__ v,
    float* __restrict__ rq, float* __restrict__ rk, float* __restrict__ rv)
{
    const float* s; float* d;
    if (blockIdx.z == 0)      { s = q; d = rq; }
    else if (blockIdx.z == 1) { s = k; d = rk; }
    else                      { s = v; d = rv; }
    size_t i = ((size_t)blockIdx.x * 256 + threadIdx.x) * 4;
    float4 x = *(const float4*)&s[i];
    x.x = rnd_tf32(x.x); x.y = rnd_tf32(x.y);
    x.z = rnd_tf32(x.z); x.w = rnd_tf32(x.w);
    *(float4*)&d[i] = x;
}

__global__ __launch_bounds__(256) void round_weights(
    const float* __restrict__ w0, const float* __restrict__ w1,
    const float* __restrict__ w2, const float* __restrict__ w3,
    float* __restrict__ dst)
{
    const float* s;
    if (blockIdx.z == 0)      s = w0;
    else if (blockIdx.z == 1) s = w1;
    else if (blockIdx.z == 2) s = w2;
    else                      s = w3;
    size_t i = ((size_t)blockIdx.x * 256 + threadIdx.x) * 4;
    float4 x = *(const float4*)&s[i];
    x.x = rnd_tf32(x.x); x.y = rnd_tf32(x.y);
    x.z = rnd_tf32(x.z); x.w = rnd_tf32(x.w);
    *(float4*)&dst[(size_t)blockIdx.z * DMODEL * DMODEL + i] = x;
}

// =================== tf32 mma.sync NT GEMM body ==============================
// C[M,N] = A[M,K] @ W[N,K]^T + bias.  CTA 128x128, BK=32, 3-stage cp.async.
// Inputs must be tf32-pre-rounded; no cvt in the hot loop.
#define GSTAGES 3
#define ASTRIDE 36
#define ATILE_WORDS (128 * ASTRIDE)
#define STAGE_BYTES (2 * ATILE_WORDS * 4)
#define GEMM_SMEM (GSTAGES * STAGE_BYTES)   // 110592

template <bool ROUND_OUT>
static __device__ __forceinline__ void gemm_body(
    float* dynf,
    const float* __restrict__ A, const float* __restrict__ W,
    const float* __restrict__ bias, float* __restrict__ C,
    int M, int N, int K, int bm, int bn)
{
    const uint32_t smbase = smem_u32(dynf);
    const int tid = threadIdx.x;
    const int wid = tid >> 5;
    const int lane = tid & 31;
    const int g = lane >> 2;
    const int t = lane & 3;
    const int warp_m = wid >> 2;
    const int warp_n = wid & 3;
    const int mbase = warp_m * 64;
    const int nbase = warp_n * 32;
    const int lrow = ((lane >> 3) & 1) * 8 + (lane & 7);
    const int lcolb = (lane >> 4) * 16;

    const int nchunks = K / 32;

    const float* Abase = A + (size_t)bm * K;
    const float* Bbase = W + (size_t)bn * K;

    auto load_chunk = [&](int c, int s) {
        uint32_t sa = smbase + s * STAGE_BYTES;
        uint32_t sb = sa + ATILE_WORDS * 4;
        const float* Ap = Abase + c * 32;
        const float* Bp = Bbase + c * 32;
#pragma unroll
        for (int v = 0; v < 4; v++) {
            int idx = tid + 256 * v;
            int row = idx >> 3;
            int seg = idx & 7;
            uint32_t off = (uint32_t)(row * ASTRIDE + seg * 4) * 4;
            CP_ASYNC16(sa + off, Ap + (size_t)row * K + seg * 4);
            CP_ASYNC16(sb + off, Bp + (size_t)row * K + seg * 4);
        }
    };

    float c[4][4][4];
#pragma unroll
    for (int mt = 0; mt < 4; mt++)
#pragma unroll
        for (int nt = 0; nt < 4; nt++)
#pragma unroll
            for (int r = 0; r < 4; r++) c[mt][nt][r] = 0.f;

    load_chunk(0, 0); CP_COMMIT();
    load_chunk(1, 1); CP_COMMIT();

    int s = 0;
    int sl = 2;
    for (int i = 0; i < nchunks; i++) {
        CP_WAIT1();
        __syncthreads();

        const int nxt = i + 2;
        if (nxt < nchunks) load_chunk(nxt, sl);
        CP_COMMIT();

        const uint32_t sa = smbase + s * STAGE_BYTES;
        const float* Bs = dynf + s * (STAGE_BYTES / 4) + ATILE_WORDS;

#pragma unroll
        for (int ks = 0; ks < 4; ks++) {
            uint32_t a[4][4];
#pragma unroll
            for (int mt = 0; mt < 4; mt++) {
                uint32_t addr = sa +
                    (uint32_t)((mbase + mt * 16 + lrow) * ASTRIDE + ks * 8) * 4 + lcolb;
                LDSM_X4(a[mt][0], a[mt][1], a[mt][2], a[mt][3], addr);
            }
            uint32_t b[4][2];
#pragma unroll
            for (int nt = 0; nt < 4; nt++) {
                const float* bp = Bs + (nbase + nt * 8 + g) * ASTRIDE + ks * 8 + t;
                b[nt][0] = __float_as_uint(bp[0]);
                b[nt][1] = __float_as_uint(bp[4]);
            }
#pragma unroll
            for (int mt = 0; mt < 4; mt++)
#pragma unroll
                for (int nt = 0; nt < 4; nt++)
                    MMA_TF32(c[mt][nt], a[mt], b[nt]);
        }

        s = (s == GSTAGES - 1) ? 0 : s + 1;
        sl = (sl == GSTAGES - 1) ? 0 : sl + 1;
    }

#pragma unroll
    for (int mt = 0; mt < 4; mt++) {
        const int r0 = bm + mbase + mt * 16 + g;
#pragma unroll
        for (int nt = 0; nt < 4; nt++) {
            const int col = bn + nbase + nt * 8 + 2 * t;
            const float b0 = bias[col], b1 = bias[col + 1];
            float2 o0 = make_float2(c[mt][nt][0] + b0, c[mt][nt][1] + b1);
            float2 o1 = make_float2(c[mt][nt][2] + b0, c[mt][nt][3] + b1);
            if (ROUND_OUT) {
                o0.x = rnd_tf32(o0.x); o0.y = rnd_tf32(o0.y);
                o1.x = rnd_tf32(o1.x); o1.y = rnd_tf32(o1.y);
            }
            *(float2*)&C[(size_t)r0 * N + col] = o0;
            *(float2*)&C[(size_t)(r0 + 8) * N + col] = o1;
        }
    }
}

// final dense GEMM: fp32 output, no rounding
__global__ __launch_bounds__(256, 2) void gemm_mma(
    const float* __restrict__ A, const float* __restrict__ W,
    const float* __restrict__ bias, float* __restrict__ C,
    int M, int N, int K)
{
    extern __shared__ float dynf[];
    gemm_body<false>(dynf, A, W, bias, C, M, N, K,
                     blockIdx.y * 128, blockIdx.x * 128);
}

// merged Q/K/V projection; outputs tf32-rounded for the attention kernel
__global__ __launch_bounds__(256, 2) void qkv_mma(
    const float* __restrict__ Aq, const float* __restrict__ Ak, const float* __restrict__ Av,
    const float* __restrict__ Wall,
    const float* __restrict__ bq, const float* __restrict__ bk, const float* __restrict__ bv,
    float* __restrict__ Cq, float* __restrict__ Ck, float* __restrict__ Cv)
{
    extern __shared__ float dynf[];
    const float* A; const float* bias; float* C;
    if (blockIdx.z == 0)      { A = Aq; bias = bq; C = Cq; }
    else if (blockIdx.z == 1) { A = Ak; bias = bk; C = Ck; }
    else                      { A = Av; bias = bv; C = Cv; }
    const float* W = Wall + (size_t)blockIdx.z * DMODEL * DMODEL;
    gemm_body<true>(dynf, A, W, bias, C, MROWS, DMODEL, DMODEL,
                    blockIdx.y * 128, blockIdx.x * 128);
}

// =================== tensor-core attention ===================================
// Q/K/V arrive tf32-pre-rounded: no cvt on their fragments. Output X is
// stored tf32-rounded for the dense GEMM.
#define AQT 128
#define AKT 64
#define QSTR 76
#define KSTR 68
#define VSTR 68
#define QWORDS (AQT * QSTR)            // 9728
#define KVWORDS (AKT * KSTR)           // 4352
#define STAGEW (2 * KVWORDS)           // 8704
#define ATTN_SMEM ((QWORDS + 2 * STAGEW + SLEN) * 4)  // 112640 B

__global__ __launch_bounds__(256, 2) void attn_tc(
    const float* __restrict__ Q, const float* __restrict__ K,
    const float* __restrict__ V, const float* __restrict__ pol,
    float* __restrict__ X)
{
    extern __shared__ float sf[];
    const uint32_t smbase = smem_u32(sf);

    const int qt = blockIdx.x;
    const int h  = blockIdx.y;
    const int b  = blockIdx.z;
    const int tid = threadIdx.x;
    const int wid = tid >> 5;
    const int lane = tid & 31;
    const int g = lane >> 2;
    const int t = lane & 3;
    const int lrow = ((lane >> 3) & 1) * 8 + (lane & 7);
    const int lcolb = (lane >> 4) * 16;

    const float* Qg = Q + ((size_t)(b * SLEN + qt * AQT)) * DMODEL + h * DK;
    const float* Kg = K + ((size_t)b * SLEN) * DMODEL + h * DK;
    const float* Vg = V + ((size_t)b * SLEN) * DMODEL + h * DK;
    const float* pg = pol + (size_t)b * SLEN;

    {
#pragma unroll
        for (int v = 0; v < 8; v++) {
            int idx = tid + 256 * v;
            int row = idx >> 4;
            int seg = idx & 15;
            CP_ASYNC16(smbase + (uint32_t)(row * QSTR + seg * 4) * 4,
                       Qg + (size_t)row * DMODEL + seg * 4);
        }
        CP_ASYNC16(smbase + (uint32_t)(QWORDS + 2 * STAGEW + tid * 4) * 4,
                   pg + tid * 4);
    }
    auto load_kv = [&](int kt, int s) {
        uint32_t kb = smbase + (uint32_t)(QWORDS + s * STAGEW) * 4;
        uint32_t vb = kb + KVWORDS * 4;
        const float* Kp = Kg + (size_t)(kt * AKT) * DMODEL;
        const float* Vp = Vg + (size_t)(kt * AKT) * DMODEL;
#pragma unroll
        for (int v = 0; v < 4; v++) {
            int idx = tid + 256 * v;
            int row = idx >> 4;
            int seg = idx & 15;
            uint32_t off = (uint32_t)(row * KSTR + seg * 4) * 4;
            CP_ASYNC16(kb + off, Kp + (size_t)row * DMODEL + seg * 4);
            CP_ASYNC16(vb + off, Vp + (size_t)row * DMODEL + seg * 4);
        }
    };
    load_kv(0, 0); CP_COMMIT();
    load_kv(1, 1); CP_COMMIT();

    uint32_t aq[8][4];
    float O[8][4];
    float rs0 = 0.f, rs1 = 0.f;
#pragma unroll
    for (int n2 = 0; n2 < 8; n2++)
#pragma unroll
        for (int r = 0; r < 4; r++) O[n2][r] = 0.f;

    const int ntiles = SLEN / AKT;  // 16
    for (int kt = 0; kt < ntiles; kt++) {
        const int s = kt & 1;
        CP_WAIT1();
        __syncthreads();

        if (kt == 0) {
#pragma unroll
            for (int ks = 0; ks < 8; ks++) {
                uint32_t addr = smbase +
                    (uint32_t)((wid * 16 + lrow) * QSTR + ks * 8) * 4 + lcolb;
                LDSM_X4(aq[ks][0], aq[ks][1], aq[ks][2], aq[ks][3], addr);
            }
        }

        const float* Ksf = sf + QWORDS + s * STAGEW;
        const float* Vsf = Ksf + KVWORDS;

        float sc[8][4];
#pragma unroll
        for (int nt = 0; nt < 8; nt++)
#pragma unroll
            for (int r = 0; r < 4; r++) sc[nt][r] = 0.f;

#pragma unroll
        for (int ks = 0; ks < 8; ks++) {
#pragma unroll
            for (int nt = 0; nt < 8; nt++) {
                const float* bp = Ksf + (nt * 8 + g) * KSTR + ks * 8 + t;
                uint32_t b0 = __float_as_uint(bp[0]);
                uint32_t b1 = __float_as_uint(bp[4]);
                MMA_TF32_4(sc[nt], aq[ks][0], aq[ks][1], aq[ks][2], aq[ks][3], b0, b1);
            }
        }

        const float* pk = sf + QWORDS + 2 * STAGEW + kt * AKT;
#pragma unroll
        for (int nt = 0; nt < 8; nt++) {
            float p0 = pk[nt * 8 + 2 * t];
            float p1 = pk[nt * 8 + 2 * t + 1];
            float e0 = __expf(sc[nt][0] * 0.125f) * p0;
            float e1 = __expf(sc[nt][1] * 0.125f) * p1;
            float e2 = __expf(sc[nt][2] * 0.125f) * p0;
            float e3 = __expf(sc[nt][3] * 0.125f) * p1;
            rs0 += e0 + e1;
            rs1 += e2 + e3;
            sc[nt][0] = __uint_as_float(f2tf32(e0));
            sc[nt][1] = __uint_as_float(f2tf32(e1));
            sc[nt][2] = __uint_as_float(f2tf32(e2));
            sc[nt][3] = __uint_as_float(f2tf32(e3));
        }

#pragma unroll
        for (int k2 = 0; k2 < 8; k2++) {
            const float* vrow = Vsf + (k2 * 8 + 2 * t) * VSTR;
            uint32_t pa0 = __float_as_uint(sc[k2][0]);
            uint32_t pa1 = __float_as_uint(sc[k2][2]);
            uint32_t pa2 = __float_as_uint(sc[k2][1]);
            uint32_t pa3 = __float_as_uint(sc[k2][3]);
#pragma unroll
            for (int n2 = 0; n2 < 8; n2++) {
                uint32_t b0 = __float_as_uint(vrow[n2 * 8 + g]);
                uint32_t b1 = __float_as_uint(vrow[VSTR + n2 * 8 + g]);
                MMA_TF32_4(O[n2], pa0, pa1, pa2, pa3, b0, b1);
            }
        }

        __syncthreads();
        if (kt + 2 < ntiles) load_kv(kt + 2, s);
        CP_COMMIT();
    }

    rs0 += __shfl_xor_sync(0xffffffffu, rs0, 1);
    rs0 += __shfl_xor_sync(0xffffffffu, rs0, 2);
    rs1 += __shfl_xor_sync(0xffffffffu, rs1, 1);
    rs1 += __shfl_xor_sync(0xffffffffu, rs1, 2);
    const float i0 = 1.f / (rs0 + 1e-6f);
    const float i1 = 1.f / (rs1 + 1e-6f);

    float* Xg = X + ((size_t)(b * SLEN + qt * AQT + wid * 16)) * DMODEL + h * DK;
#pragma unroll
    for (int n2 = 0; n2 < 8; n2++) {
        int col = n2 * 8 + 2 * t;
        float2 o0 = make_float2(rnd_tf32(O[n2][0] * i0), rnd_tf32(O[n2][1] * i0));
        float2 o1 = make_float2(rnd_tf32(O[n2][2] * i1), rnd_tf32(O[n2][3] * i1));
        *(float2*)&Xg[(size_t)g * DMODEL + col] = o0;
        *(float2*)&Xg[(size_t)(g + 8) * DMODEL + col] = o1;
    }
}

// ---------------- launch ------------------------------------------------------
extern "C" void kernel_launch(void* const* d_in, const int* in_sizes, int n_in,
                              void* d_out, int out_size)
{
    const float* query   = (const float*)d_in[0];
    const float* key     = (const float*)d_in[1];
    const float* value   = (const float*)d_in[2];
    const float* policy  = (const float*)d_in[3];
    const float* wq_w    = (const float*)d_in[4];
    const float* wq_b    = (const float*)d_in[5];
    const float* wk_w    = (const float*)d_in[6];
    const float* wk_b    = (const float*)d_in[7];
    const float* wv_w    = (const float*)d_in[8];
    const float* wv_b    = (const float*)d_in[9];
    const float* dense_w = (const float*)d_in[10];
    const float* dense_b = (const float*)d_in[11];
    float* out = (float*)d_out;

    float *Qp, *Kp, *Vp, *Xp, *Rq, *Rk, *Rv, *Rw;
    cudaGetSymbolAddress((void**)&Qp, g_Q);
    cudaGetSymbolAddress((void**)&Kp, g_K);
    cudaGetSymbolAddress((void**)&Vp, g_V);
    cudaGetSymbolAddress((void**)&Xp, g_X);
    cudaGetSymbolAddress((void**)&Rq, g_Rq);
    cudaGetSymbolAddress((void**)&Rk, g_Rk);
    cudaGetSymbolAddress((void**)&Rv, g_Rv);
    cudaGetSymbolAddress((void**)&Rw, g_Rw);

    cudaFuncSetAttribute(gemm_mma, cudaFuncAttributeMaxDynamicSharedMemorySize, GEMM_SMEM);
    cudaFuncSetAttribute(qkv_mma,  cudaFuncAttributeMaxDynamicSharedMemorySize, GEMM_SMEM);
    cudaFuncSetAttribute(attn_tc,  cudaFuncAttributeMaxDynamicSharedMemorySize, ATTN_SMEM);

    // pre-round activations + weights to tf32 grid
    dim3 gri(MROWS * DMODEL / 1024, 1, 3);   // (8192, 1, 3)
    round_inputs<<<gri, 256>>>(query, key, value, Rq, Rk, Rv);
    dim3 grw(DMODEL * DMODEL / 1024, 1, 4);  // (1024, 1, 4)
    round_weights<<<grw, 256>>>(wq_w, wk_w, wv_w, dense_w, Rw);

    dim3 gqkv(DMODEL / 128, MROWS / 128, 3);  // (8, 64, 3)
    qkv_mma<<<gqkv, 256, GEMM_SMEM>>>(Rq, Rk, Rv, Rw,
                                      wq_b, wk_b, wv_b,
                                      Qp, Kp, Vp);

    dim3 gattn(SLEN / AQT, NHEADS, BATCH);  // (8, 16, 8)
    attn_tc<<<gattn, 256, ATTN_SMEM>>>(Qp, Kp, Vp, policy, Xp);

    dim3 gblk(DMODEL / 128, MROWS / 128);  // (8, 64)
    gemm_mma<<<gblk, 256, GEMM_SMEM>>>(Xp, Rw + (size_t)3 * DMODEL * DMODEL,
                                       dense_b, out, MROWS, DMODEL, DMODEL);
}

// round 16
// speedup vs baseline: 4.1771x; 1.0246x over previous
#include <cuda_runtime.h>
#include <cuda_bf16.h>
#include <cstdint>
#include <cstddef>

// Problem constants
#define BATCH 8
#define SLEN 1024
#define DMODEL 1024
#define NHEADS 16
#define DK 64
#define MROWS (BATCH * SLEN)   // 8192

// ---------------- scratch (device globals; no allocation allowed) ------------
__device__ float g_Q[MROWS * DMODEL];
__device__ float g_K[MROWS * DMODEL];
__device__ float g_V[MROWS * DMODEL];
__device__ float g_X[MROWS * DMODEL];
// tf32-pre-rounded copies
__device__ float g_Rq[MROWS * DMODEL];
__device__ float g_Rk[MROWS * DMODEL];
__device__ float g_Rv[MROWS * DMODEL];
__device__ float g_Rw[4 * DMODEL * DMODEL];   // wq, wk, wv, dense

// =================== PTX helpers =============================================
static __device__ __forceinline__ uint32_t smem_u32(const void* p) {
    uint32_t a;
    asm("{ .reg .u64 t; cvta.to.shared.u64 t, %1; cvt.u32.u64 %0, t; }"
        : "=r"(a) : "l"(p));
    return a;
}

#define CP_ASYNC16(dst, src) \
    asm volatile("cp.async.cg.shared.global [%0], [%1], 16;" \
                 :: "r"(dst), "l"(src) : "memory")
#define CP_COMMIT() asm volatile("cp.async.commit_group;" ::: "memory")
#define CP_WAIT1()  asm volatile("cp.async.wait_group 1;" ::: "memory")

static __device__ __forceinline__ uint32_t f2tf32(float x) {
    uint32_t r;
    asm("cvt.rna.tf32.f32 %0, %1;" : "=r"(r) : "f"(x));
    return r;
}
static __device__ __forceinline__ float rnd_tf32(float x) {
    return __uint_as_float(f2tf32(x));
}

#define LDSM_X4(r0, r1, r2, r3, addr) \
    asm volatile("ldmatrix.sync.aligned.m8n8.x4.shared.b16 {%0,%1,%2,%3}, [%4];" \
                 : "=r"(r0), "=r"(r1), "=r"(r2), "=r"(r3) : "r"(addr))

#define MMA_TF32(c, a, b) \
    asm volatile("mma.sync.aligned.m16n8k8.row.col.f32.tf32.tf32.f32 " \
                 "{%0,%1,%2,%3}, {%4,%5,%6,%7}, {%8,%9}, {%0,%1,%2,%3};" \
                 : "+f"((c)[0]), "+f"((c)[1]), "+f"((c)[2]), "+f"((c)[3]) \
                 : "r"((a)[0]), "r"((a)[1]), "r"((a)[2]), "r"((a)[3]), \
                   "r"((b)[0]), "r"((b)[1]))

#define MMA_TF32_4(c, a0, a1, a2, a3, b0, b1) \
    asm volatile("mma.sync.aligned.m16n8k8.row.col.f32.tf32.tf32.f32 " \
                 "{%0,%1,%2,%3}, {%4,%5,%6,%7}, {%8,%9}, {%0,%1,%2,%3};" \
                 : "+f"((c)[0]), "+f"((c)[1]), "+f"((c)[2]), "+f"((c)[3]) \
                 : "r"(a0), "r"(a1), "r"(a2), "r"(a3), "r"(b0), "r"(b1))

// =================== tf32 pre-round passes ===================================
__global__ __launch_bounds__(256) void round_inputs(
    const float* __restrict__ q, const float* __restrict__ k,
    const float* __restrict__ v,
    float* __restrict__ rq, float* __restrict__ rk, float* __restrict__ rv)
{
    const float* s; float* d;
    if (blockIdx.z == 0)      { s = q; d = rq; }
    else if (blockIdx.z == 1) { s = k; d = rk; }
    else                      { s = v; d = rv; }
    size_t i = ((size_t)blockIdx.x * 256 + threadIdx.x) * 4;
    float4 x = *(const float4*)&s[i];
    x.x = rnd_tf32(x.x); x.y = rnd_tf32(x.y);
    x.z = rnd_tf32(x.z); x.w = rnd_tf32(x.w);
    *(float4*)&d[i] = x;
}

__global__ __launch_bounds__(256) void round_weights(
    const float* __restrict__ w0, const float* __restrict__ w1,
    const float* __restrict__ w2, const float* __restrict__ w3,
    float* __restrict__ dst)
{
    const float* s;
    if (blockIdx.z == 0)      s = w0;
    else if (blockIdx.z == 1) s = w1;
    else if (blockIdx.z == 2) s = w2;
    else                      s = w3;
    size_t i = ((size_t)blockIdx.x * 256 + threadIdx.x) * 4;
    float4 x = *(const float4*)&s[i];
    x.x = rnd_tf32(x.x); x.y = rnd_tf32(x.y);
    x.z = rnd_tf32(x.z); x.w = rnd_tf32(x.w);
    *(float4*)&dst[(size_t)blockIdx.z * DMODEL * DMODEL + i] = x;
}

// =================== tf32 mma.sync NT GEMM body ==============================
// C[M,N] = A[M,K] @ W[N,K]^T + bias.  CTA 128x128, BK=32, 3-stage cp.async.
// A and B fragments both via ldmatrix (b16-reinterpret trick).
#define GSTAGES 3
#define ASTRIDE 36
#define ATILE_WORDS (128 * ASTRIDE)
#define STAGE_BYTES (2 * ATILE_WORDS * 4)
#define GEMM_SMEM (GSTAGES * STAGE_BYTES)   // 110592

template <bool ROUND_OUT>
static __device__ __forceinline__ void gemm_body(
    float* dynf,
    const float* __restrict__ A, const float* __restrict__ W,
    const float* __restrict__ bias, float* __restrict__ C,
    int M, int N, int K, int bm, int bn)
{
    const uint32_t smbase = smem_u32(dynf);
    const int tid = threadIdx.x;
    const int wid = tid >> 5;
    const int lane = tid & 31;
    const int g = lane >> 2;
    const int t = lane & 3;
    const int warp_m = wid >> 2;
    const int warp_n = wid & 3;
    const int mbase = warp_m * 64;
    const int nbase = warp_n * 32;
    const int lrow = ((lane >> 3) & 1) * 8 + (lane & 7);
    const int lcolb = (lane >> 4) * 16;
    // ldmatrix-B addressing: 4 matrices left-to-right, rows = lane&7
    const int brow = lane & 7;
    const int bmatb = (lane >> 3) * 16;    // byte offset of this lane's matrix

    const int nchunks = K / 32;

    const float* Abase = A + (size_t)bm * K;
    const float* Bbase = W + (size_t)bn * K;

    auto load_chunk = [&](int c, int s) {
        uint32_t sa = smbase + s * STAGE_BYTES;
        uint32_t sb = sa + ATILE_WORDS * 4;
        const float* Ap = Abase + c * 32;
        const float* Bp = Bbase + c * 32;
#pragma unroll
        for (int v = 0; v < 4; v++) {
            int idx = tid + 256 * v;
            int row = idx >> 3;
            int seg = idx & 7;
            uint32_t off = (uint32_t)(row * ASTRIDE + seg * 4) * 4;
            CP_ASYNC16(sa + off, Ap + (size_t)row * K + seg * 4);
            CP_ASYNC16(sb + off, Bp + (size_t)row * K + seg * 4);
        }
    };

    float c[4][4][4];
#pragma unroll
    for (int mt = 0; mt < 4; mt++)
#pragma unroll
        for (int nt = 0; nt < 4; nt++)
#pragma unroll
            for (int r = 0; r < 4; r++) c[mt][nt][r] = 0.f;

    load_chunk(0, 0); CP_COMMIT();
    load_chunk(1, 1); CP_COMMIT();

    int s = 0;
    int sl = 2;
    for (int i = 0; i < nchunks; i++) {
        CP_WAIT1();
        __syncthreads();

        const int nxt = i + 2;
        if (nxt < nchunks) load_chunk(nxt, sl);
        CP_COMMIT();

        const uint32_t sa = smbase + s * STAGE_BYTES;
        const uint32_t sb = sa + ATILE_WORDS * 4;

#pragma unroll
        for (int ks2 = 0; ks2 < 2; ks2++) {
            // B fragments for 2 k-steps via ldmatrix x4:
            // matrices: [keys nbase+nt*8.., d-cols ks2*16 + {0-3,4-7,8-11,12-15}]
            uint32_t bf[4][4];
#pragma unroll
            for (int nt = 0; nt < 4; nt++) {
                uint32_t baddr = sb +
                    (uint32_t)((nbase + nt * 8 + brow) * ASTRIDE) * 4 +
                    ks2 * 64 + bmatb;
                LDSM_X4(bf[nt][0], bf[nt][1], bf[nt][2], bf[nt][3], baddr);
            }
#pragma unroll
            for (int kk = 0; kk < 2; kk++) {
                const int ks = ks2 * 2 + kk;
                uint32_t a[4][4];
#pragma unroll
                for (int mt = 0; mt < 4; mt++) {
                    uint32_t addr = sa +
                        (uint32_t)((mbase + mt * 16 + lrow) * ASTRIDE + ks * 8) * 4 + lcolb;
                    LDSM_X4(a[mt][0], a[mt][1], a[mt][2], a[mt][3], addr);
                }
#pragma unroll
                for (int mt = 0; mt < 4; mt++)
#pragma unroll
                    for (int nt = 0; nt < 4; nt++)
                        MMA_TF32_4(c[mt][nt], a[mt][0], a[mt][1], a[mt][2], a[mt][3],
                                   bf[nt][kk * 2], bf[nt][kk * 2 + 1]);
            }
        }

        s = (s == GSTAGES - 1) ? 0 : s + 1;
        sl = (sl == GSTAGES - 1) ? 0 : sl + 1;
    }

#pragma unroll
    for (int mt = 0; mt < 4; mt++) {
        const int r0 = bm + mbase + mt * 16 + g;
#pragma unroll
        for (int nt = 0; nt < 4; nt++) {
            const int col = bn + nbase + nt * 8 + 2 * t;
            const float b0 = bias[col], b1 = bias[col + 1];
            float2 o0 = make_float2(c[mt][nt][0] + b0, c[mt][nt][1] + b1);
            float2 o1 = make_float2(c[mt][nt][2] + b0, c[mt][nt][3] + b1);
            if (ROUND_OUT) {
                o0.x = rnd_tf32(o0.x); o0.y = rnd_tf32(o0.y);
                o1.x = rnd_tf32(o1.x); o1.y = rnd_tf32(o1.y);
            }
            *(float2*)&C[(size_t)r0 * N + col] = o0;
            *(float2*)&C[(size_t)(r0 + 8) * N + col] = o1;
        }
    }
}

__global__ __launch_bounds__(256, 2) void gemm_mma(
    const float* __restrict__ A, const float* __restrict__ W,
    const float* __restrict__ bias, float* __restrict__ C,
    int M, int N, int K)
{
    extern __shared__ float dynf[];
    gemm_body<false>(dynf, A, W, bias, C, M, N, K,
                     blockIdx.y * 128, blockIdx.x * 128);
}

__global__ __launch_bounds__(256, 2) void qkv_mma(
    const float* __restrict__ Aq, const float* __restrict__ Ak, const float* __restrict__ Av,
    const float* __restrict__ Wall,
    const float* __restrict__ bq, const float* __restrict__ bk, const float* __restrict__ bv,
    float* __restrict__ Cq, float* __restrict__ Ck, float* __restrict__ Cv)
{
    extern __shared__ float dynf[];
    const float* A; const float* bias; float* C;
    if (blockIdx.z == 0)      { A = Aq; bias = bq; C = Cq; }
    else if (blockIdx.z == 1) { A = Ak; bias = bk; C = Ck; }
    else                      { A = Av; bias = bv; C = Cv; }
    const float* W = Wall + (size_t)blockIdx.z * DMODEL * DMODEL;
    gemm_body<true>(dynf, A, W, bias, C, MROWS, DMODEL, DMODEL,
                    blockIdx.y * 128, blockIdx.x * 128);
}

// =================== tensor-core attention ===================================
#define AQT 128
#define AKT 64
#define QSTR 76
#define KSTR 68
#define VSTR 68
#define QWORDS (AQT * QSTR)            // 9728
#define KVWORDS (AKT * KSTR)           // 4352
#define STAGEW (2 * KVWORDS)           // 8704
#define ATTN_SMEM ((QWORDS + 2 * STAGEW + SLEN) * 4)  // 112640 B

__global__ __launch_bounds__(256, 2) void attn_tc(
    const float* __restrict__ Q, const float* __restrict__ K,
    const float* __restrict__ V, const float* __restrict__ pol,
    float* __restrict__ X)
{
    extern __shared__ float sf[];
    const uint32_t smbase = smem_u32(sf);

    const int qt = blockIdx.x;
    const int h  = blockIdx.y;
    const int b  = blockIdx.z;
    const int tid = threadIdx.x;
    const int wid = tid >> 5;
    const int lane = tid & 31;
    const int g = lane >> 2;
    const int t = lane & 3;
    const int lrow = ((lane >> 3) & 1) * 8 + (lane & 7);
    const int lcolb = (lane >> 4) * 16;
    const int brow = lane & 7;
    const int bmatb = (lane >> 3) * 16;

    const float* Qg = Q + ((size_t)(b * SLEN + qt * AQT)) * DMODEL + h * DK;
    const float* Kg = K + ((size_t)b * SLEN) * DMODEL + h * DK;
    const float* Vg = V + ((size_t)b * SLEN) * DMODEL + h * DK;
    const float* pg = pol + (size_t)b * SLEN;

    {
#pragma unroll
        for (int v = 0; v < 8; v++) {
            int idx = tid + 256 * v;
            int row = idx >> 4;
            int seg = idx & 15;
            CP_ASYNC16(smbase + (uint32_t)(row * QSTR + seg * 4) * 4,
                       Qg + (size_t)row * DMODEL + seg * 4);
        }
        CP_ASYNC16(smbase + (uint32_t)(QWORDS + 2 * STAGEW + tid * 4) * 4,
                   pg + tid * 4);
    }
    auto load_kv = [&](int kt, int s) {
        uint32_t kb = smbase + (uint32_t)(QWORDS + s * STAGEW) * 4;
        uint32_t vb = kb + KVWORDS * 4;
        const float* Kp = Kg + (size_t)(kt * AKT) * DMODEL;
        const float* Vp = Vg + (size_t)(kt * AKT) * DMODEL;
#pragma unroll
        for (int v = 0; v < 4; v++) {
            int idx = tid + 256 * v;
            int row = idx >> 4;
            int seg = idx & 15;
            uint32_t off = (uint32_t)(row * KSTR + seg * 4) * 4;
            CP_ASYNC16(kb + off, Kp + (size_t)row * DMODEL + seg * 4);
            CP_ASYNC16(vb + off, Vp + (size_t)row * DMODEL + seg * 4);
        }
    };
    load_kv(0, 0); CP_COMMIT();
    load_kv(1, 1); CP_COMMIT();

    uint32_t aq[8][4];
    float O[8][4];
    float rs0 = 0.f, rs1 = 0.f;
#pragma unroll
    for (int n2 = 0; n2 < 8; n2++)
#pragma unroll
        for (int r = 0; r < 4; r++) O[n2][r] = 0.f;

    const int ntiles = SLEN / AKT;  // 16
    for (int kt = 0; kt < ntiles; kt++) {
        const int s = kt & 1;
        CP_WAIT1();
        __syncthreads();

        if (kt == 0) {
#pragma unroll
            for (int ks = 0; ks < 8; ks++) {
                uint32_t addr = smbase +
                    (uint32_t)((wid * 16 + lrow) * QSTR + ks * 8) * 4 + lcolb;
                LDSM_X4(aq[ks][0], aq[ks][1], aq[ks][2], aq[ks][3], addr);
            }
        }

        const uint32_t kbu = smbase + (uint32_t)(QWORDS + s * STAGEW) * 4;
        const float* Vsf = sf + QWORDS + s * STAGEW + KVWORDS;

        // ---- phase 1: S = Q K^T, K fragments via ldmatrix x4 ----
        float sc[8][4];
#pragma unroll
        for (int nt = 0; nt < 8; nt++)
#pragma unroll
            for (int r = 0; r < 4; r++) sc[nt][r] = 0.f;

#pragma unroll
        for (int nt = 0; nt < 8; nt++) {
#pragma unroll
            for (int ks2 = 0; ks2 < 4; ks2++) {
                uint32_t r0, r1, r2, r3;
                uint32_t baddr = kbu +
                    (uint32_t)((nt * 8 + brow) * KSTR) * 4 + ks2 * 64 + bmatb;
                LDSM_X4(r0, r1, r2, r3, baddr);
                MMA_TF32_4(sc[nt], aq[2 * ks2][0], aq[2 * ks2][1],
                           aq[2 * ks2][2], aq[2 * ks2][3], r0, r1);
                MMA_TF32_4(sc[nt], aq[2 * ks2 + 1][0], aq[2 * ks2 + 1][1],
                           aq[2 * ks2 + 1][2], aq[2 * ks2 + 1][3], r2, r3);
            }
        }

        const float* pk = sf + QWORDS + 2 * STAGEW + kt * AKT;
#pragma unroll
        for (int nt = 0; nt < 8; nt++) {
            float p0 = pk[nt * 8 + 2 * t];
            float p1 = pk[nt * 8 + 2 * t + 1];
            float e0 = __expf(sc[nt][0] * 0.125f) * p0;
            float e1 = __expf(sc[nt][1] * 0.125f) * p1;
            float e2 = __expf(sc[nt][2] * 0.125f) * p0;
            float e3 = __expf(sc[nt][3] * 0.125f) * p1;
            rs0 += e0 + e1;
            rs1 += e2 + e3;
            sc[nt][0] = __uint_as_float(f2tf32(e0));
            sc[nt][1] = __uint_as_float(f2tf32(e1));
            sc[nt][2] = __uint_as_float(f2tf32(e2));
            sc[nt][3] = __uint_as_float(f2tf32(e3));
        }

        // ---- phase 2: O += P V (V scalar LDS; transposed pattern) ----
#pragma unroll
        for (int k2 = 0; k2 < 8; k2++) {
            const float* vrow = Vsf + (k2 * 8 + 2 * t) * VSTR;
            uint32_t pa0 = __float_as_uint(sc[k2][0]);
            uint32_t pa1 = __float_as_uint(sc[k2][2]);
            uint32_t pa2 = __float_as_uint(sc[k2][1]);
            uint32_t pa3 = __float_as_uint(sc[k2][3]);
#pragma unroll
            for (int n2 = 0; n2 < 8; n2++) {
                uint32_t b0 = __float_as_uint(vrow[n2 * 8 + g]);
                uint32_t b1 = __float_as_uint(vrow[VSTR + n2 * 8 + g]);
                MMA_TF32_4(O[n2], pa0, pa1, pa2, pa3, b0, b1);
            }
        }

        __syncthreads();
        if (kt + 2 < ntiles) load_kv(kt + 2, s);
        CP_COMMIT();
    }

    rs0 += __shfl_xor_sync(0xffffffffu, rs0, 1);
    rs0 += __shfl_xor_sync(0xffffffffu, rs0, 2);
    rs1 += __shfl_xor_sync(0xffffffffu, rs1, 1);
    rs1 += __shfl_xor_sync(0xffffffffu, rs1, 2);
    const float i0 = 1.f / (rs0 + 1e-6f);
    const float i1 = 1.f / (rs1 + 1e-6f);

    float* Xg = X + ((size_t)(b * SLEN + qt * AQT + wid * 16)) * DMODEL + h * DK;
#pragma unroll
    for (int n2 = 0; n2 < 8; n2++) {
        int col = n2 * 8 + 2 * t;
        float2 o0 = make_float2(rnd_tf32(O[n2][0] * i0), rnd_tf32(O[n2][1] * i0));
        float2 o1 = make_float2(rnd_tf32(O[n2][2] * i1), rnd_tf32(O[n2][3] * i1));
        *(float2*)&Xg[(size_t)g * DMODEL + col] = o0;
        *(float2*)&Xg[(size_t)(g + 8) * DMODEL + col] = o1;
    }
}

// ---------------- launch ------------------------------------------------------
extern "C" void kernel_launch(void* const* d_in, const int* in_sizes, int n_in,
                              void* d_out, int out_size)
{
    const float* query   = (const float*)d_in[0];
    const float* key     = (const float*)d_in[1];
    const float* value   = (const float*)d_in[2];
    const float* policy  = (const float*)d_in[3];
    const float* wq_w    = (const float*)d_in[4];
    const float* wq_b    = (const float*)d_in[5];
    const float* wk_w    = (const float*)d_in[6];
    const float* wk_b    = (const float*)d_in[7];
    const float* wv_w    = (const float*)d_in[8];
    const float* wv_b    = (const float*)d_in[9];
    const float* dense_w = (const float*)d_in[10];
    const float* dense_b = (const float*)d_in[11];
    float* out = (float*)d_out;

    float *Qp, *Kp, *Vp, *Xp, *Rq, *Rk, *Rv, *Rw;
    cudaGetSymbolAddress((void**)&Qp, g_Q);
    cudaGetSymbolAddress((void**)&Kp, g_K);
    cudaGetSymbolAddress((void**)&Vp, g_V);
    cudaGetSymbolAddress((void**)&Xp, g_X);
    cudaGetSymbolAddress((void**)&Rq, g_Rq);
    cudaGetSymbolAddress((void**)&Rk, g_Rk);
    cudaGetSymbolAddress((void**)&Rv, g_Rv);
    cudaGetSymbolAddress((void**)&Rw, g_Rw);

    cudaFuncSetAttribute(gemm_mma, cudaFuncAttributeMaxDynamicSharedMemorySize, GEMM_SMEM);
    cudaFuncSetAttribute(qkv_mma,  cudaFuncAttributeMaxDynamicSharedMemorySize, GEMM_SMEM);
    cudaFuncSetAttribute(attn_tc,  cudaFuncAttributeMaxDynamicSharedMemorySize, ATTN_SMEM);

    dim3 gri(MROWS * DMODEL / 1024, 1, 3);   // (8192, 1, 3)
    round_inputs<<<gri, 256>>>(query, key, value, Rq, Rk, Rv);
    dim3 grw(DMODEL * DMODEL / 1024, 1, 4);  // (1024, 1, 4)
    round_weights<<<grw, 256>>>(wq_w, wk_w, wv_w, dense_w, Rw);

    dim3 gqkv(DMODEL / 128, MROWS / 128, 3);  // (8, 64, 3)
    qkv_mma<<<gqkv, 256, GEMM_SMEM>>>(Rq, Rk, Rv, Rw,
                                      wq_b, wk_b, wv_b,
                                      Qp, Kp, Vp);

    dim3 gattn(SLEN / AQT, NHEADS, BATCH);  // (8, 16, 8)
    attn_tc<<<gattn, 256, ATTN_SMEM>>>(Qp, Kp, Vp, policy, Xp);

    dim3 gblk(DMODEL / 128, MROWS / 128);  // (8, 64)
    gemm_mma<<<gblk, 256, GEMM_SMEM>>>(Xp, Rw + (size_t)3 * DMODEL * DMODEL,
                                       dense_b, out, MROWS, DMODEL, DMODEL);
}